// round 9
// baseline (speedup 1.0000x reference)
#include <cuda_runtime.h>
#include <math.h>

#define HW    4096
#define DM    64
#define DS    16
#define NB    4

// Scratch (device globals; no allocation allowed)
__device__ float g_h[64];
__device__ float g_part[512];         // 256 blocks x (sum, sumsq)
__device__ float g_delta[NB*DM*HW];   // 4MB
__device__ float g_Bval[NB*DS*HW];    // 1MB
__device__ float g_Cval[NB*DS*HW];    // 1MB

typedef unsigned long long ull;

__device__ __forceinline__ ull pk2(float x) {
    ull r; asm("mov.b64 %0,{%1,%1};" : "=l"(r) : "f"(x)); return r;
}
__device__ __forceinline__ void fma2(ull &a, ull b, ull c) {
    asm("fma.rn.f32x2 %0,%1,%2,%0;" : "+l"(a) : "l"(b), "l"(c));
}
__device__ __forceinline__ float2 up2(ull a) {
    float2 v; asm("mov.b64 {%0,%1},%2;" : "=f"(v.x), "=f"(v.y) : "l"(a)); return v;
}

// ---------------------------------------------------------------------------
// K0: spectral-derivative circular kernel h[n] (exact, fp64 accumulation)
// ---------------------------------------------------------------------------
__global__ void k_init_h() {
    int n = threadIdx.x;  // 0..63
    double acc = 0.0;
    for (int m = 1; m < 32; m++) {
        double km = 2.0 * 3.141592653589793238 * (double)m / 64.0;
        acc += km * sin(km * (double)n);
    }
    g_h[n] = (float)(-acc * 2.0 / 64.0);
}

// ---------------------------------------------------------------------------
// K1: GroupNorm partial sums. 256 blocks (16 per (b,g)), deterministic.
// ---------------------------------------------------------------------------
__global__ void __launch_bounds__(256) k_stats(const float* __restrict__ u) {
    int blk = blockIdx.x;
    int bg = blk >> 4, seg = blk & 15;
    const float4* base = (const float4*)(u + bg * 65536 + seg * 4096);
    float s = 0.f, s2 = 0.f;
    #pragma unroll
    for (int i = threadIdx.x; i < 1024; i += 256) {
        float4 v = base[i];
        s += v.x + v.y + v.z + v.w;
        s2 = fmaf(v.x, v.x, s2); s2 = fmaf(v.y, v.y, s2);
        s2 = fmaf(v.z, v.z, s2); s2 = fmaf(v.w, v.w, s2);
    }
    for (int o = 16; o; o >>= 1) {
        s  += __shfl_down_sync(0xFFFFFFFFu, s,  o);
        s2 += __shfl_down_sync(0xFFFFFFFFu, s2, o);
    }
    __shared__ float ss[8], ss2[8];
    int w = threadIdx.x >> 5, l = threadIdx.x & 31;
    if (l == 0) { ss[w] = s; ss2[w] = s2; }
    __syncthreads();
    if (threadIdx.x == 0) {
        float S = 0.f, S2 = 0.f;
        #pragma unroll
        for (int i = 0; i < 8; i++) { S += ss[i]; S2 += ss2[i]; }
        g_part[blk * 2]     = S;
        g_part[blk * 2 + 1] = S2;
    }
}

// ---------------------------------------------------------------------------
// K2: fused GroupNorm + circular 3x3 convs, packed f32x2 over oc pairs.
// x operands pre-duplicated in shared as ull pairs (zero packing ALU).
// Weights transposed [tap_icl][oc] stride 98, single buffer, reg-prefetch.
// ---------------------------------------------------------------------------
#define WST 98
__global__ void __launch_bounds__(128) k_conv(
        const float* __restrict__ u,
        const float* __restrict__ gamma, const float* __restrict__ beta,
        const float* __restrict__ wd, const float* __restrict__ bd,
        const float* __restrict__ wB, const float* __restrict__ wC,
        const float* __restrict__ dtp) {
    __shared__ float ws[36 * WST];       // 14.1KB: [icl*9+tap][oc]
    __shared__ ull   xs2[64 * 60];       // 30.7KB: duplicated halo pairs
    __shared__ float cs_scale[64], cs_shift[64];

    int bx = blockIdx.x;
    int b  = bx >> 7;
    int t  = bx & 127;
    int y0 = (t >> 4) * 8;
    int x0 = (t & 15) * 4;

    int tid = threadIdx.x;
    int ocg = tid >> 3;            // 0..15
    int pxg = tid & 7;             // 0..7
    int oc0 = ocg * 6;
    int py0 = (pxg >> 1) * 2;      // 0,2,4,6
    int px0 = (pxg & 1) * 2;       // 0,2

    // finalize GroupNorm stats from partials
    if (tid < 64) {
        int bg = b * 4 + (tid >> 4);
        float S = 0.f, S2 = 0.f;
        #pragma unroll
        for (int i = 0; i < 16; i++) {
            S  += g_part[(bg * 16 + i) * 2];
            S2 += g_part[(bg * 16 + i) * 2 + 1];
        }
        float mu  = S  * (1.f / 65536.f);
        float var = S2 * (1.f / 65536.f) - mu * mu;
        float rs = rsqrtf(var + 1e-5f) * gamma[tid];
        cs_scale[tid] = rs;
        cs_shift[tid] = beta[tid] - mu * rs;
    }
    __syncthreads();

    // per-thread LDG slots: l4 = tid + 128*s, s<7, valid if l4 < 864
    int l_oc[7], l_rem[7];
    #pragma unroll
    for (int s = 0; s < 7; s++) {
        int l4 = tid + 128 * s;
        l_oc[s]  = l4 / 9;
        l_rem[s] = l4 - l_oc[s] * 9;
    }
    float4 rg[7];

    // LDG chunk 0
    #pragma unroll
    for (int s = 0; s < 7; s++) {
        if (tid + 128 * s < 864) {
            int oc = l_oc[s], rem = l_rem[s];
            const float4* src;
            if (oc < 64)      src = (const float4*)wd + oc * 144 + rem;
            else if (oc < 80) src = (const float4*)wB + (oc - 64) * 144 + rem;
            else              src = (const float4*)wC + (oc - 80) * 144 + rem;
            rg[s] = __ldg(src);
        }
    }

    // normalized halo for all 64 channels, duplicated pairs: 64 x 10 x 6
    #pragma unroll 1
    for (int l = tid; l < 3840; l += 128) {
        int icl = l / 60; int r = l - icl * 60;
        int yy = r / 6, xx = r - yy * 6;
        int gy = (y0 + yy - 1) & 63;
        int gx = (x0 + xx - 1) & 63;
        float v = u[((b * 64 + icl) * 64 + gy) * 64 + gx];
        xs2[l] = pk2(fmaf(v, cs_scale[icl], cs_shift[icl]));
    }

    // STS chunk 0 (transposed)
    #pragma unroll
    for (int s = 0; s < 7; s++) {
        if (tid + 128 * s < 864) {
            int oc = l_oc[s], rem = l_rem[s];
            ws[(rem * 4 + 0) * WST + oc] = rg[s].x;
            ws[(rem * 4 + 1) * WST + oc] = rg[s].y;
            ws[(rem * 4 + 2) * WST + oc] = rg[s].z;
            ws[(rem * 4 + 3) * WST + oc] = rg[s].w;
        }
    }
    __syncthreads();

    ull acc[3][4];   // oc pairs (oc0+2p, oc0+2p+1) x 4 px
    #pragma unroll
    for (int p = 0; p < 3; p++)
        #pragma unroll
        for (int q = 0; q < 4; q++) acc[p][q] = 0ull;

    #pragma unroll 1
    for (int c = 0; c < 16; c++) {
        if (c < 15) {
            int nc = c + 1;
            #pragma unroll
            for (int s = 0; s < 7; s++) {
                if (tid + 128 * s < 864) {
                    int oc = l_oc[s], rem = l_rem[s];
                    const float4* src;
                    if (oc < 64)      src = (const float4*)wd + oc * 144 + nc * 9 + rem;
                    else if (oc < 80) src = (const float4*)wB + (oc - 64) * 144 + nc * 9 + rem;
                    else              src = (const float4*)wC + (oc - 80) * 144 + nc * 9 + rem;
                    rg[s] = __ldg(src);
                }
            }
        }

        #pragma unroll
        for (int icl = 0; icl < 4; icl++) {
            int ic = c * 4 + icl;
            const ull* xp = xs2 + ic * 60 + py0 * 6 + px0;
            ull xv[4][4];
            #pragma unroll
            for (int rr = 0; rr < 4; rr++)
                #pragma unroll
                for (int cc = 0; cc < 4; cc++) xv[rr][cc] = xp[rr * 6 + cc];
            #pragma unroll
            for (int dy = 0; dy < 3; dy++) {
                #pragma unroll
                for (int dx = 0; dx < 3; dx++) {
                    const float* row = ws + (icl * 9 + dy * 3 + dx) * WST + oc0;
                    ull w01 = *(const ull*)(row);
                    ull w23 = *(const ull*)(row + 2);
                    ull w45 = *(const ull*)(row + 4);
                    ull pa = xv[dy][dx];
                    ull pb = xv[dy][dx + 1];
                    ull pc = xv[dy + 1][dx];
                    ull pd = xv[dy + 1][dx + 1];
                    fma2(acc[0][0], w01, pa); fma2(acc[0][1], w01, pb);
                    fma2(acc[0][2], w01, pc); fma2(acc[0][3], w01, pd);
                    fma2(acc[1][0], w23, pa); fma2(acc[1][1], w23, pb);
                    fma2(acc[1][2], w23, pc); fma2(acc[1][3], w23, pd);
                    fma2(acc[2][0], w45, pa); fma2(acc[2][1], w45, pb);
                    fma2(acc[2][2], w45, pc); fma2(acc[2][3], w45, pd);
                }
            }
        }
        __syncthreads();

        if (c < 15) {
            #pragma unroll
            for (int s = 0; s < 7; s++) {
                if (tid + 128 * s < 864) {
                    int oc = l_oc[s], rem = l_rem[s];
                    ws[(rem * 4 + 0) * WST + oc] = rg[s].x;
                    ws[(rem * 4 + 1) * WST + oc] = rg[s].y;
                    ws[(rem * 4 + 2) * WST + oc] = rg[s].z;
                    ws[(rem * 4 + 3) * WST + oc] = rg[s].w;
                }
            }
            __syncthreads();
        }
    }

    float dtv = __ldg(dtp);
    int yb = y0 + py0, xb = x0 + px0;
    int pix[4] = { yb * 64 + xb, yb * 64 + xb + 1,
                   (yb + 1) * 64 + xb, (yb + 1) * 64 + xb + 1 };

    #pragma unroll
    for (int p = 0; p < 3; p++) {
        #pragma unroll
        for (int half = 0; half < 2; half++) {
            int oc = oc0 + 2 * p + half;
            float av[4];
            #pragma unroll
            for (int q = 0; q < 4; q++) {
                float2 v = up2(acc[p][q]);
                av[q] = half ? v.y : v.x;
            }
            if (oc < 64) {
                float bias = bd[oc] + dtv;
                float* dst = g_delta + (b * 64 + oc) * HW;
                #pragma unroll
                for (int q = 0; q < 4; q++) {
                    float v = av[q] + bias;
                    float sp = (v > 0.f) ? (v + log1pf(expf(-v))) : log1pf(expf(v));
                    sp = fminf(fmaxf(sp, 1e-4f), 5.0f);
                    dst[pix[q]] = sp;
                }
            } else if (oc < 80) {
                float* dst = g_Bval + (b * 16 + (oc - 64)) * HW;
                #pragma unroll
                for (int q = 0; q < 4; q++) dst[pix[q]] = av[q];
            } else {
                float* dst = g_Cval + (b * 16 + (oc - 80)) * HW;
                #pragma unroll
                for (int q = 0; q < 4; q++) dst[pix[q]] = av[q];
            }
        }
    }
}

// ---------------------------------------------------------------------------
// K3: per-(b,d,n) plane: circulant matmuls via fp32x2 with ALL packed
// operands pre-staged in shared (Xt transposed for row pairs, hp2 ull
// broadcast pairs). 128 thr, 4096 blocks, 3 blocks/SM.
// ---------------------------------------------------------------------------
__global__ void __launch_bounds__(128, 3) k_update(
        const float* __restrict__ u, const float* __restrict__ sprev,
        const float* __restrict__ logA, float* __restrict__ out) {
    __shared__ float Xs[64 * 68];    // X[r][c] at r*68 + c + 2*(c>>5)
    __shared__ float Xt[64 * 66];    // X^T: Xt[k*66 + r] = X[r][k]
    __shared__ ull   hp2[144];       // (h[i&63], h[i&63])

    int tid = threadIdx.x;
    int bp  = blockIdx.x;            // b*1024 + d*16 + n
    int b = bp >> 10, d = (bp >> 4) & 63, n = bp & 15;

    int p0 = (((b * 3 + 0) * 64 + d) * 16 + n) * HW;
    int p1 = p0 + 64 * 16 * HW;
    int p2 = p1 + 64 * 16 * HW;
    const float4* m0p4 = (const float4*)(sprev + p0);

    #pragma unroll
    for (int s = 0; s < 8; s++) {
        int l4 = tid + 128 * s;              // < 1024
        float4 v = m0p4[l4];
        int idx = l4 * 4;
        int r = idx >> 6, cc = idx & 63;
        float* xsp = &Xs[r * 68 + cc + 2 * (cc >> 5)];
        *(float2*)xsp       = make_float2(v.x, v.y);
        *(float2*)(xsp + 2) = make_float2(v.z, v.w);
        Xt[(cc + 0) * 66 + r] = v.x;
        Xt[(cc + 1) * 66 + r] = v.y;
        Xt[(cc + 2) * 66 + r] = v.z;
        Xt[(cc + 3) * 66 + r] = v.w;
    }
    if (tid < 72) {
        hp2[tid]      = pk2(g_h[tid & 63]);
        hp2[tid + 72] = pk2(g_h[(tid + 72) & 63]);
    }
    __syncthreads();

    int rg = tid >> 3, cg = tid & 7;    // rg 0..15, cg 0..7
    int r0 = rg * 4, c0 = cg * 8;
    int gap2 = 2 * (c0 >> 5);

    float Ad = -expf(__ldg(&logA[d * 16 + n]));
    int off_bd = (b * 64 + d) * HW;
    int off_bn = (b * 16 + n) * HW;
    const int so = NB * DM * HW;

    float Abs[32];   // A_bar carried into phase 2

    // ===== Phase 1: Gx[r][c] = sum_k X[r][k] h[c-k] =====
    {
        ull a[2][8];
        #pragma unroll
        for (int p = 0; p < 2; p++)
            #pragma unroll
            for (int j = 0; j < 8; j++) a[p][j] = 0ull;

        #pragma unroll 1
        for (int k8 = 0; k8 < 64; k8 += 8) {
            ull hl[15];
            int hbase = c0 - k8 + 57;   // in [1,127]
            #pragma unroll
            for (int m = 0; m < 15; m++) hl[m] = hp2[hbase + m];
            ull xp0[8], xp1[8];
            #pragma unroll
            for (int kk = 0; kk < 8; kk++) {
                int kb = (k8 + kk) * 66;
                xp0[kk] = *(const ull*)&Xt[kb + r0];
                xp1[kk] = *(const ull*)&Xt[kb + r0 + 2];
            }
            #pragma unroll
            for (int kk = 0; kk < 8; kk++)
                #pragma unroll
                for (int j = 0; j < 8; j++) {
                    fma2(a[0][j], xp0[kk], hl[j - kk + 7]);
                    fma2(a[1][j], xp1[kk], hl[j - kk + 7]);
                }
        }

        // epilogue: m0_new, mx_new (compute+stash A_bar)
        #pragma unroll
        for (int i = 0; i < 4; i++) {
            int row = r0 + i;
            int off = row * 64 + c0;
            float4 dv0 = *(const float4*)(g_delta + off_bd + off);
            float4 dv1 = *(const float4*)(g_delta + off_bd + off + 4);
            float4 uv0 = *(const float4*)(u + off_bd + off);
            float4 uv1 = *(const float4*)(u + off_bd + off + 4);
            float4 bv0 = *(const float4*)(g_Bval + off_bn + off);
            float4 bv1 = *(const float4*)(g_Bval + off_bn + off + 4);
            float4 mx0 = *(const float4*)(sprev + p1 + off);
            float4 mx1 = *(const float4*)(sprev + p1 + off + 4);
            float dd[8] = { dv0.x, dv0.y, dv0.z, dv0.w, dv1.x, dv1.y, dv1.z, dv1.w };
            float uu[8] = { uv0.x, uv0.y, uv0.z, uv0.w, uv1.x, uv1.y, uv1.z, uv1.w };
            float bb[8] = { bv0.x, bv0.y, bv0.z, bv0.w, bv1.x, bv1.y, bv1.z, bv1.w };
            float mx[8] = { mx0.x, mx0.y, mx0.z, mx0.w, mx1.x, mx1.y, mx1.z, mx1.w };
            float m0n[8], mxn[8];
            #pragma unroll
            for (int j = 0; j < 8; j++) {
                float2 tt = up2(a[i >> 1][j]);
                float gx = (i & 1) ? tt.y : tt.x;
                float m0v = Xs[row * 68 + c0 + j + gap2];
                float Ab = __expf(dd[j] * Ad);
                Abs[i * 8 + j] = Ab;
                m0n[j] = fmaf(Ab, m0v, dd[j] * bb[j] * uu[j]);
                mxn[j] = Ab * (mx[j] - gx);
            }
            *(float4*)(out + so + p0 + off)     = make_float4(m0n[0], m0n[1], m0n[2], m0n[3]);
            *(float4*)(out + so + p0 + off + 4) = make_float4(m0n[4], m0n[5], m0n[6], m0n[7]);
            *(float4*)(out + so + p1 + off)     = make_float4(mxn[0], mxn[1], mxn[2], mxn[3]);
            *(float4*)(out + so + p1 + off + 4) = make_float4(mxn[4], mxn[5], mxn[6], mxn[7]);
        }
    }

    // ===== Phase 2: Gy[r][c] = sum_k h[r-k] X[k][c], pack over col pairs ====
    {
        ull g2[4][4];
        #pragma unroll
        for (int i = 0; i < 4; i++)
            #pragma unroll
            for (int q = 0; q < 4; q++) g2[i][q] = 0ull;

        #pragma unroll 1
        for (int k8 = 0; k8 < 64; k8 += 8) {
            ull gl[11];
            int gb = r0 - k8 + 57;      // in [1,127]
            #pragma unroll
            for (int m = 0; m < 11; m++) gl[m] = hp2[gb + m];
            #pragma unroll
            for (int kk = 0; kk < 8; kk++) {
                int ro = (k8 + kk) * 68 + c0 + gap2;   // even -> 8B aligned
                const ull* xrow = (const ull*)&Xs[ro];
                ull xq[4];
                #pragma unroll
                for (int q = 0; q < 4; q++) xq[q] = xrow[q];
                #pragma unroll
                for (int i = 0; i < 4; i++)
                    #pragma unroll
                    for (int q = 0; q < 4; q++)
                        fma2(g2[i][q], gl[i - kk + 7], xq[q]);
            }
        }

        // epilogue: my_new (A_bar from registers)
        #pragma unroll
        for (int i = 0; i < 4; i++) {
            int row = r0 + i;
            int off = row * 64 + c0;
            float4 my0 = *(const float4*)(sprev + p2 + off);
            float4 my1 = *(const float4*)(sprev + p2 + off + 4);
            float my[8] = { my0.x, my0.y, my0.z, my0.w, my1.x, my1.y, my1.z, my1.w };
            float myn[8];
            #pragma unroll
            for (int j = 0; j < 8; j++) {
                float2 tt = up2(g2[i][j >> 1]);
                float gy = (j & 1) ? tt.y : tt.x;
                myn[j] = Abs[i * 8 + j] * (my[j] - gy);
            }
            *(float4*)(out + so + p2 + off)     = make_float4(myn[0], myn[1], myn[2], myn[3]);
            *(float4*)(out + so + p2 + off + 4) = make_float4(myn[4], myn[5], myn[6], myn[7]);
        }
    }
}

// ---------------------------------------------------------------------------
// K4: y[b,d,p] = sum_n m0_new[b,d,n,p] * C_val[b,n,p] + u*D[d]  (float4)
// ---------------------------------------------------------------------------
__global__ void k_y(const float* __restrict__ u, const float* __restrict__ Dp,
                    float* __restrict__ out) {
    int idx4 = blockIdx.x * 256 + threadIdx.x;   // < 262144
    int b = idx4 >> 16;
    int d = (idx4 >> 10) & 63;
    int p4 = idx4 & 1023;
    const int so = NB * DM * HW;
    const float4* m0n = (const float4*)(out + so + ((b * 3 * 64 + d) * 16) * HW) + p4;
    const float4* Cv  = (const float4*)(g_Cval + (b * 16) * HW) + p4;
    float4 a = make_float4(0.f, 0.f, 0.f, 0.f);
    #pragma unroll
    for (int nn = 0; nn < 16; nn++) {
        float4 m = m0n[nn * 1024];
        float4 c = Cv[nn * 1024];
        a.x = fmaf(m.x, c.x, a.x); a.y = fmaf(m.y, c.y, a.y);
        a.z = fmaf(m.z, c.z, a.z); a.w = fmaf(m.w, c.w, a.w);
    }
    float Dd = Dp[d];
    float4 uv = ((const float4*)u)[idx4];
    a.x = fmaf(uv.x, Dd, a.x); a.y = fmaf(uv.y, Dd, a.y);
    a.z = fmaf(uv.z, Dd, a.z); a.w = fmaf(uv.w, Dd, a.w);
    ((float4*)out)[idx4] = a;
}

// ---------------------------------------------------------------------------
extern "C" void kernel_launch(void* const* d_in, const int* in_sizes, int n_in,
                              void* d_out, int out_size) {
    const float* u     = (const float*)d_in[0];
    const float* sprev = (const float*)d_in[1];
    const float* gamma = (const float*)d_in[2];
    const float* beta  = (const float*)d_in[3];
    const float* wd    = (const float*)d_in[4];
    const float* bd    = (const float*)d_in[5];
    const float* wB    = (const float*)d_in[6];
    const float* wC    = (const float*)d_in[7];
    const float* logA  = (const float*)d_in[8];
    const float* Dp    = (const float*)d_in[9];
    const float* dt    = (const float*)d_in[10];
    float* out = (float*)d_out;

    k_init_h<<<1, 64>>>();
    k_stats<<<256, 256>>>(u);
    k_conv<<<512, 128>>>(u, gamma, beta, wd, bd, wB, wC, dt);
    k_update<<<4096, 128>>>(u, sprev, logA, out);
    k_y<<<1024, 256>>>(u, Dp, out);
}

// round 10
// speedup vs baseline: 1.1608x; 1.1608x over previous
#include <cuda_runtime.h>
#include <math.h>

#define HW    4096
#define DM    64
#define DS    16
#define NB    4

// Scratch (device globals; no allocation allowed)
__device__ float g_h[64];
__device__ float g_part[512];         // 256 blocks x (sum, sumsq)
__device__ float g_delta[NB*DM*HW];   // 4MB
__device__ float g_Bval[NB*DS*HW];    // 1MB
__device__ float g_Cval[NB*DS*HW];    // 1MB

typedef unsigned long long ull;

__device__ __forceinline__ ull pk2(float x) {
    ull r; asm("mov.b64 %0,{%1,%1};" : "=l"(r) : "f"(x)); return r;
}
__device__ __forceinline__ void fma2(ull &a, ull b, ull c) {
    asm("fma.rn.f32x2 %0,%1,%2,%0;" : "+l"(a) : "l"(b), "l"(c));
}
__device__ __forceinline__ float2 up2(ull a) {
    float2 v; asm("mov.b64 {%0,%1},%2;" : "=f"(v.x), "=f"(v.y) : "l"(a)); return v;
}

// ---------------------------------------------------------------------------
// K0: spectral-derivative circular kernel h[n] (exact, fp64 accumulation)
// ---------------------------------------------------------------------------
__global__ void k_init_h() {
    int n = threadIdx.x;  // 0..63
    double acc = 0.0;
    for (int m = 1; m < 32; m++) {
        double km = 2.0 * 3.141592653589793238 * (double)m / 64.0;
        acc += km * sin(km * (double)n);
    }
    g_h[n] = (float)(-acc * 2.0 / 64.0);
}

// ---------------------------------------------------------------------------
// K1: GroupNorm partial sums. 256 blocks (16 per (b,g)), deterministic.
// ---------------------------------------------------------------------------
__global__ void __launch_bounds__(256) k_stats(const float* __restrict__ u) {
    int blk = blockIdx.x;
    int bg = blk >> 4, seg = blk & 15;
    const float4* base = (const float4*)(u + bg * 65536 + seg * 4096);
    float s = 0.f, s2 = 0.f;
    #pragma unroll
    for (int i = threadIdx.x; i < 1024; i += 256) {
        float4 v = base[i];
        s += v.x + v.y + v.z + v.w;
        s2 = fmaf(v.x, v.x, s2); s2 = fmaf(v.y, v.y, s2);
        s2 = fmaf(v.z, v.z, s2); s2 = fmaf(v.w, v.w, s2);
    }
    for (int o = 16; o; o >>= 1) {
        s  += __shfl_down_sync(0xFFFFFFFFu, s,  o);
        s2 += __shfl_down_sync(0xFFFFFFFFu, s2, o);
    }
    __shared__ float ss[8], ss2[8];
    int w = threadIdx.x >> 5, l = threadIdx.x & 31;
    if (l == 0) { ss[w] = s; ss2[w] = s2; }
    __syncthreads();
    if (threadIdx.x == 0) {
        float S = 0.f, S2 = 0.f;
        #pragma unroll
        for (int i = 0; i < 8; i++) { S += ss[i]; S2 += ss2[i]; }
        g_part[blk * 2]     = S;
        g_part[blk * 2 + 1] = S2;
    }
}

// ---------------------------------------------------------------------------
// K2: fused GroupNorm + circular 3x3 convs, packed f32x2 over oc pairs.
// (R8 configuration: transposed double-buffered weights, float2 x + pk2.)
// ---------------------------------------------------------------------------
#define WST 98
__global__ void __launch_bounds__(128) k_conv(
        const float* __restrict__ u,
        const float* __restrict__ gamma, const float* __restrict__ beta,
        const float* __restrict__ wd, const float* __restrict__ bd,
        const float* __restrict__ wB, const float* __restrict__ wC,
        const float* __restrict__ dtp) {
    __shared__ float ws2[2][36 * WST];   // 28.2KB
    __shared__ float xs[64 * 60];        // 15.4KB
    __shared__ float cs_scale[64], cs_shift[64];

    int bx = blockIdx.x;
    int b  = bx >> 7;
    int t  = bx & 127;
    int y0 = (t >> 4) * 8;
    int x0 = (t & 15) * 4;

    int tid = threadIdx.x;
    int ocg = tid >> 3;
    int pxg = tid & 7;
    int oc0 = ocg * 6;
    int py0 = (pxg >> 1) * 2;
    int px0 = (pxg & 1) * 2;

    if (tid < 64) {
        int bg = b * 4 + (tid >> 4);
        float S = 0.f, S2 = 0.f;
        #pragma unroll
        for (int i = 0; i < 16; i++) {
            S  += g_part[(bg * 16 + i) * 2];
            S2 += g_part[(bg * 16 + i) * 2 + 1];
        }
        float mu  = S  * (1.f / 65536.f);
        float var = S2 * (1.f / 65536.f) - mu * mu;
        float rs = rsqrtf(var + 1e-5f) * gamma[tid];
        cs_scale[tid] = rs;
        cs_shift[tid] = beta[tid] - mu * rs;
    }
    __syncthreads();

    int l_oc[7], l_rem[7];
    #pragma unroll
    for (int s = 0; s < 7; s++) {
        int l4 = tid + 128 * s;
        l_oc[s]  = l4 / 9;
        l_rem[s] = l4 - l_oc[s] * 9;
    }
    float4 rg[7];

    #pragma unroll
    for (int s = 0; s < 7; s++) {
        if (tid + 128 * s < 864) {
            int oc = l_oc[s], rem = l_rem[s];
            const float4* src;
            if (oc < 64)      src = (const float4*)wd + oc * 144 + rem;
            else if (oc < 80) src = (const float4*)wB + (oc - 64) * 144 + rem;
            else              src = (const float4*)wC + (oc - 80) * 144 + rem;
            rg[s] = __ldg(src);
        }
    }

    #pragma unroll 1
    for (int l = tid; l < 3840; l += 128) {
        int icl = l / 60; int r = l - icl * 60;
        int yy = r / 6, xx = r - yy * 6;
        int gy = (y0 + yy - 1) & 63;
        int gx = (x0 + xx - 1) & 63;
        float v = u[((b * 64 + icl) * 64 + gy) * 64 + gx];
        xs[l] = fmaf(v, cs_scale[icl], cs_shift[icl]);
    }

    #pragma unroll
    for (int s = 0; s < 7; s++) {
        if (tid + 128 * s < 864) {
            int oc = l_oc[s], rem = l_rem[s];
            ws2[0][(rem * 4 + 0) * WST + oc] = rg[s].x;
            ws2[0][(rem * 4 + 1) * WST + oc] = rg[s].y;
            ws2[0][(rem * 4 + 2) * WST + oc] = rg[s].z;
            ws2[0][(rem * 4 + 3) * WST + oc] = rg[s].w;
        }
    }
    __syncthreads();

    ull acc[3][4];
    #pragma unroll
    for (int p = 0; p < 3; p++)
        #pragma unroll
        for (int q = 0; q < 4; q++) acc[p][q] = 0ull;

    #pragma unroll 1
    for (int c = 0; c < 16; c++) {
        if (c < 15) {
            int nc = c + 1;
            #pragma unroll
            for (int s = 0; s < 7; s++) {
                if (tid + 128 * s < 864) {
                    int oc = l_oc[s], rem = l_rem[s];
                    const float4* src;
                    if (oc < 64)      src = (const float4*)wd + oc * 144 + nc * 9 + rem;
                    else if (oc < 80) src = (const float4*)wB + (oc - 64) * 144 + nc * 9 + rem;
                    else              src = (const float4*)wC + (oc - 80) * 144 + nc * 9 + rem;
                    rg[s] = __ldg(src);
                }
            }
        }

        const float* wsb = ws2[c & 1];
        #pragma unroll
        for (int icl = 0; icl < 4; icl++) {
            int ic = c * 4 + icl;
            const float* xp = xs + ic * 60 + py0 * 6 + px0;
            float xr[4][4];
            #pragma unroll
            for (int rr = 0; rr < 4; rr++) {
                float2 lo = *(const float2*)(xp + rr * 6);
                float2 hi = *(const float2*)(xp + rr * 6 + 2);
                xr[rr][0] = lo.x; xr[rr][1] = lo.y;
                xr[rr][2] = hi.x; xr[rr][3] = hi.y;
            }
            #pragma unroll
            for (int dy = 0; dy < 3; dy++) {
                #pragma unroll
                for (int dx = 0; dx < 3; dx++) {
                    const float* row = wsb + (icl * 9 + dy * 3 + dx) * WST + oc0;
                    ull w01 = *(const ull*)(row);
                    ull w23 = *(const ull*)(row + 2);
                    ull w45 = *(const ull*)(row + 4);
                    ull pa = pk2(xr[dy][dx]);
                    ull pb = pk2(xr[dy][dx + 1]);
                    ull pc = pk2(xr[dy + 1][dx]);
                    ull pd = pk2(xr[dy + 1][dx + 1]);
                    fma2(acc[0][0], w01, pa); fma2(acc[0][1], w01, pb);
                    fma2(acc[0][2], w01, pc); fma2(acc[0][3], w01, pd);
                    fma2(acc[1][0], w23, pa); fma2(acc[1][1], w23, pb);
                    fma2(acc[1][2], w23, pc); fma2(acc[1][3], w23, pd);
                    fma2(acc[2][0], w45, pa); fma2(acc[2][1], w45, pb);
                    fma2(acc[2][2], w45, pc); fma2(acc[2][3], w45, pd);
                }
            }
        }

        if (c < 15) {
            float* dstb = ws2[(c + 1) & 1];
            #pragma unroll
            for (int s = 0; s < 7; s++) {
                if (tid + 128 * s < 864) {
                    int oc = l_oc[s], rem = l_rem[s];
                    dstb[(rem * 4 + 0) * WST + oc] = rg[s].x;
                    dstb[(rem * 4 + 1) * WST + oc] = rg[s].y;
                    dstb[(rem * 4 + 2) * WST + oc] = rg[s].z;
                    dstb[(rem * 4 + 3) * WST + oc] = rg[s].w;
                }
            }
        }
        __syncthreads();
    }

    float dtv = __ldg(dtp);
    int yb = y0 + py0, xb = x0 + px0;
    int pix[4] = { yb * 64 + xb, yb * 64 + xb + 1,
                   (yb + 1) * 64 + xb, (yb + 1) * 64 + xb + 1 };

    #pragma unroll
    for (int p = 0; p < 3; p++) {
        #pragma unroll
        for (int half = 0; half < 2; half++) {
            int oc = oc0 + 2 * p + half;
            float av[4];
            #pragma unroll
            for (int q = 0; q < 4; q++) {
                float2 v = up2(acc[p][q]);
                av[q] = half ? v.y : v.x;
            }
            if (oc < 64) {
                float bias = bd[oc] + dtv;
                float* dst = g_delta + (b * 64 + oc) * HW;
                #pragma unroll
                for (int q = 0; q < 4; q++) {
                    float v = av[q] + bias;
                    float sp = (v > 0.f) ? (v + log1pf(expf(-v))) : log1pf(expf(v));
                    sp = fminf(fmaxf(sp, 1e-4f), 5.0f);
                    dst[pix[q]] = sp;
                }
            } else if (oc < 80) {
                float* dst = g_Bval + (b * 16 + (oc - 64)) * HW;
                #pragma unroll
                for (int q = 0; q < 4; q++) dst[pix[q]] = av[q];
            } else {
                float* dst = g_Cval + (b * 16 + (oc - 80)) * HW;
                #pragma unroll
                for (int q = 0; q < 4; q++) dst[pix[q]] = av[q];
            }
        }
    }
}

// ---------------------------------------------------------------------------
// K3: hybrid-operand circulant matmuls.
// Phase1 (Gx): X row-pairs via LDS.64 from Xt; h via scalar LDS + pk2 (ALU).
// Phase2 (Gy): 8x4 tile; X rows via LDS.64 from Xs; h via scalar + pk2;
//              A_bar recomputed from delta (L2-resident).
// ---------------------------------------------------------------------------
__global__ void __launch_bounds__(128, 3) k_update(
        const float* __restrict__ u, const float* __restrict__ sprev,
        const float* __restrict__ logA, float* __restrict__ out) {
    __shared__ float Xs[64 * 68];    // X[r][c] at r*68 + c + 2*(c>>5)
    __shared__ float Xt[64 * 66];    // X^T: Xt[k*66 + r] = X[r][k]
    __shared__ float hb[144];        // h[i mod 64]

    int tid = threadIdx.x;
    int bp  = blockIdx.x;            // b*1024 + d*16 + n
    int b = bp >> 10, d = (bp >> 4) & 63, n = bp & 15;

    int p0 = (((b * 3 + 0) * 64 + d) * 16 + n) * HW;
    int p1 = p0 + 64 * 16 * HW;
    int p2 = p1 + 64 * 16 * HW;
    const float4* m0p4 = (const float4*)(sprev + p0);

    #pragma unroll
    for (int s = 0; s < 8; s++) {
        int l4 = tid + 128 * s;              // < 1024
        float4 v = m0p4[l4];
        int idx = l4 * 4;
        int r = idx >> 6, cc = idx & 63;
        float* xsp = &Xs[r * 68 + cc + 2 * (cc >> 5)];
        *(float2*)xsp       = make_float2(v.x, v.y);
        *(float2*)(xsp + 2) = make_float2(v.z, v.w);
        Xt[(cc + 0) * 66 + r] = v.x;
        Xt[(cc + 1) * 66 + r] = v.y;
        Xt[(cc + 2) * 66 + r] = v.z;
        Xt[(cc + 3) * 66 + r] = v.w;
    }
    for (int i = tid; i < 144; i += 128) hb[i] = g_h[i & 63];
    __syncthreads();

    float Ad = -expf(__ldg(&logA[d * 16 + n]));
    int off_bd = (b * 64 + d) * HW;
    int off_bn = (b * 16 + n) * HW;
    const int so = NB * DM * HW;

    // ===== Phase 1: Gx[r][c] = sum_k X[r][k] h[c-k] =====
    {
        int rg = tid >> 3, cg = tid & 7;    // rg 0..15, cg 0..7
        int r0 = rg * 4, c0 = cg * 8;
        int gap2 = 2 * (c0 >> 5);

        ull a[2][8];
        #pragma unroll
        for (int p = 0; p < 2; p++)
            #pragma unroll
            for (int j = 0; j < 8; j++) a[p][j] = 0ull;

        #pragma unroll 1
        for (int k8 = 0; k8 < 64; k8 += 8) {
            ull hl[15];
            int hbase = c0 - k8 + 57;       // in [1,113]
            #pragma unroll
            for (int m = 0; m < 15; m++) hl[m] = pk2(hb[hbase + m]);
            #pragma unroll
            for (int kk = 0; kk < 8; kk++) {
                int kb = (k8 + kk) * 66;
                ull xp0 = *(const ull*)&Xt[kb + r0];
                ull xp1 = *(const ull*)&Xt[kb + r0 + 2];
                #pragma unroll
                for (int j = 0; j < 8; j++) {
                    fma2(a[0][j], xp0, hl[j - kk + 7]);
                    fma2(a[1][j], xp1, hl[j - kk + 7]);
                }
            }
        }

        // epilogue: m0_new, mx_new
        #pragma unroll
        for (int i = 0; i < 4; i++) {
            int row = r0 + i;
            int off = row * 64 + c0;
            float4 dv0 = *(const float4*)(g_delta + off_bd + off);
            float4 dv1 = *(const float4*)(g_delta + off_bd + off + 4);
            float4 uv0 = *(const float4*)(u + off_bd + off);
            float4 uv1 = *(const float4*)(u + off_bd + off + 4);
            float4 bv0 = *(const float4*)(g_Bval + off_bn + off);
            float4 bv1 = *(const float4*)(g_Bval + off_bn + off + 4);
            float4 mx0 = *(const float4*)(sprev + p1 + off);
            float4 mx1 = *(const float4*)(sprev + p1 + off + 4);
            float dd[8] = { dv0.x, dv0.y, dv0.z, dv0.w, dv1.x, dv1.y, dv1.z, dv1.w };
            float uu[8] = { uv0.x, uv0.y, uv0.z, uv0.w, uv1.x, uv1.y, uv1.z, uv1.w };
            float bb[8] = { bv0.x, bv0.y, bv0.z, bv0.w, bv1.x, bv1.y, bv1.z, bv1.w };
            float mx[8] = { mx0.x, mx0.y, mx0.z, mx0.w, mx1.x, mx1.y, mx1.z, mx1.w };
            float m0n[8], mxn[8];
            #pragma unroll
            for (int j = 0; j < 8; j++) {
                float2 tt = up2(a[i >> 1][j]);
                float gx = (i & 1) ? tt.y : tt.x;
                float m0v = Xs[row * 68 + c0 + j + gap2];
                float Ab = __expf(dd[j] * Ad);
                m0n[j] = fmaf(Ab, m0v, dd[j] * bb[j] * uu[j]);
                mxn[j] = Ab * (mx[j] - gx);
            }
            *(float4*)(out + so + p0 + off)     = make_float4(m0n[0], m0n[1], m0n[2], m0n[3]);
            *(float4*)(out + so + p0 + off + 4) = make_float4(m0n[4], m0n[5], m0n[6], m0n[7]);
            *(float4*)(out + so + p1 + off)     = make_float4(mxn[0], mxn[1], mxn[2], mxn[3]);
            *(float4*)(out + so + p1 + off + 4) = make_float4(mxn[4], mxn[5], mxn[6], mxn[7]);
        }
    }

    // ===== Phase 2: Gy[r][c] = sum_k h[r-k] X[k][c], 8 rows x 4 cols =====
    {
        int rg2 = tid >> 4, cg2 = tid & 15;   // rg2 0..7, cg2 0..15
        int r0 = rg2 * 8, c0 = cg2 * 4;
        int gapc = 2 * (c0 >> 5);

        ull g2[8][2];
        #pragma unroll
        for (int i = 0; i < 8; i++) { g2[i][0] = 0ull; g2[i][1] = 0ull; }

        #pragma unroll 1
        for (int k8 = 0; k8 < 64; k8 += 8) {
            ull gl[15];
            int gb = r0 - k8 + 57;            // in [1,120]
            #pragma unroll
            for (int m = 0; m < 15; m++) gl[m] = pk2(hb[gb + m]);
            #pragma unroll
            for (int kk = 0; kk < 8; kk++) {
                int ro = (k8 + kk) * 68 + c0 + gapc;   // even -> 8B aligned
                ull xq0 = *(const ull*)&Xs[ro];
                ull xq1 = *(const ull*)&Xs[ro + 2];
                #pragma unroll
                for (int i = 0; i < 8; i++) {
                    fma2(g2[i][0], gl[i - kk + 7], xq0);
                    fma2(g2[i][1], gl[i - kk + 7], xq1);
                }
            }
        }

        // epilogue: my_new (A_bar recomputed; delta tile is L2-resident)
        #pragma unroll
        for (int i = 0; i < 8; i++) {
            int row = r0 + i;
            int off = row * 64 + c0;
            float4 dv = *(const float4*)(g_delta + off_bd + off);
            float4 my = *(const float4*)(sprev + p2 + off);
            float2 t0 = up2(g2[i][0]);
            float2 t1 = up2(g2[i][1]);
            float4 myn;
            myn.x = __expf(dv.x * Ad) * (my.x - t0.x);
            myn.y = __expf(dv.y * Ad) * (my.y - t0.y);
            myn.z = __expf(dv.z * Ad) * (my.z - t1.x);
            myn.w = __expf(dv.w * Ad) * (my.w - t1.y);
            *(float4*)(out + so + p2 + off) = myn;
        }
    }
}

// ---------------------------------------------------------------------------
// K4: y[b,d,p] = sum_n m0_new[b,d,n,p] * C_val[b,n,p] + u*D[d]  (float4)
// ---------------------------------------------------------------------------
__global__ void k_y(const float* __restrict__ u, const float* __restrict__ Dp,
                    float* __restrict__ out) {
    int idx4 = blockIdx.x * 256 + threadIdx.x;   // < 262144
    int b = idx4 >> 16;
    int d = (idx4 >> 10) & 63;
    int p4 = idx4 & 1023;
    const int so = NB * DM * HW;
    const float4* m0n = (const float4*)(out + so + ((b * 3 * 64 + d) * 16) * HW) + p4;
    const float4* Cv  = (const float4*)(g_Cval + (b * 16) * HW) + p4;
    float4 a = make_float4(0.f, 0.f, 0.f, 0.f);
    #pragma unroll
    for (int nn = 0; nn < 16; nn++) {
        float4 m = m0n[nn * 1024];
        float4 c = Cv[nn * 1024];
        a.x = fmaf(m.x, c.x, a.x); a.y = fmaf(m.y, c.y, a.y);
        a.z = fmaf(m.z, c.z, a.z); a.w = fmaf(m.w, c.w, a.w);
    }
    float Dd = Dp[d];
    float4 uv = ((const float4*)u)[idx4];
    a.x = fmaf(uv.x, Dd, a.x); a.y = fmaf(uv.y, Dd, a.y);
    a.z = fmaf(uv.z, Dd, a.z); a.w = fmaf(uv.w, Dd, a.w);
    ((float4*)out)[idx4] = a;
}

// ---------------------------------------------------------------------------
extern "C" void kernel_launch(void* const* d_in, const int* in_sizes, int n_in,
                              void* d_out, int out_size) {
    const float* u     = (const float*)d_in[0];
    const float* sprev = (const float*)d_in[1];
    const float* gamma = (const float*)d_in[2];
    const float* beta  = (const float*)d_in[3];
    const float* wd    = (const float*)d_in[4];
    const float* bd    = (const float*)d_in[5];
    const float* wB    = (const float*)d_in[6];
    const float* wC    = (const float*)d_in[7];
    const float* logA  = (const float*)d_in[8];
    const float* Dp    = (const float*)d_in[9];
    const float* dt    = (const float*)d_in[10];
    float* out = (float*)d_out;

    k_init_h<<<1, 64>>>();
    k_stats<<<256, 256>>>(u);
    k_conv<<<512, 128>>>(u, gamma, beta, wd, bd, wB, wC, dt);
    k_update<<<4096, 128>>>(u, sprev, logA, out);
    k_y<<<1024, 256>>>(u, Dp, out);
}

// round 11
// speedup vs baseline: 1.1703x; 1.0082x over previous
#include <cuda_runtime.h>
#include <math.h>

#define HW    4096
#define DM    64
#define DS    16
#define NB    4

// Scratch (device globals; no allocation allowed)
__device__ float g_h[64];
__device__ float g_part[512];         // 256 blocks x (sum, sumsq)
__device__ float g_delta[NB*DM*HW];   // 4MB
__device__ float g_Bval[NB*DS*HW];    // 1MB
__device__ float g_Cval[NB*DS*HW];    // 1MB

typedef unsigned long long ull;

__device__ __forceinline__ ull pk2(float x) {
    ull r; asm("mov.b64 %0,{%1,%1};" : "=l"(r) : "f"(x)); return r;
}
__device__ __forceinline__ ull pk(float lo, float hi) {
    ull r; asm("mov.b64 %0,{%1,%2};" : "=l"(r) : "f"(lo), "f"(hi)); return r;
}
__device__ __forceinline__ void fma2(ull &a, ull b, ull c) {
    asm("fma.rn.f32x2 %0,%1,%2,%0;" : "+l"(a) : "l"(b), "l"(c));
}
__device__ __forceinline__ float2 up2(ull a) {
    float2 v; asm("mov.b64 {%0,%1},%2;" : "=f"(v.x), "=f"(v.y) : "l"(a)); return v;
}

// ---------------------------------------------------------------------------
// K0: spectral-derivative circular kernel h[n] (exact, fp64 accumulation)
// ---------------------------------------------------------------------------
__global__ void k_init_h() {
    int n = threadIdx.x;  // 0..63
    double acc = 0.0;
    for (int m = 1; m < 32; m++) {
        double km = 2.0 * 3.141592653589793238 * (double)m / 64.0;
        acc += km * sin(km * (double)n);
    }
    g_h[n] = (float)(-acc * 2.0 / 64.0);
}

// ---------------------------------------------------------------------------
// K1: GroupNorm partial sums. 256 blocks (16 per (b,g)), deterministic.
// ---------------------------------------------------------------------------
__global__ void __launch_bounds__(256) k_stats(const float* __restrict__ u) {
    int blk = blockIdx.x;
    int bg = blk >> 4, seg = blk & 15;
    const float4* base = (const float4*)(u + bg * 65536 + seg * 4096);
    float s = 0.f, s2 = 0.f;
    #pragma unroll
    for (int i = threadIdx.x; i < 1024; i += 256) {
        float4 v = base[i];
        s += v.x + v.y + v.z + v.w;
        s2 = fmaf(v.x, v.x, s2); s2 = fmaf(v.y, v.y, s2);
        s2 = fmaf(v.z, v.z, s2); s2 = fmaf(v.w, v.w, s2);
    }
    for (int o = 16; o; o >>= 1) {
        s  += __shfl_down_sync(0xFFFFFFFFu, s,  o);
        s2 += __shfl_down_sync(0xFFFFFFFFu, s2, o);
    }
    __shared__ float ss[8], ss2[8];
    int w = threadIdx.x >> 5, l = threadIdx.x & 31;
    if (l == 0) { ss[w] = s; ss2[w] = s2; }
    __syncthreads();
    if (threadIdx.x == 0) {
        float S = 0.f, S2 = 0.f;
        #pragma unroll
        for (int i = 0; i < 8; i++) { S += ss[i]; S2 += ss2[i]; }
        g_part[blk * 2]     = S;
        g_part[blk * 2 + 1] = S2;
    }
}

// ---------------------------------------------------------------------------
// K2: fused GroupNorm + circular 3x3 convs, packed f32x2 over oc pairs.
// (R8 configuration: transposed double-buffered weights, float2 x + pk2.)
// ---------------------------------------------------------------------------
#define WST 98
__global__ void __launch_bounds__(128) k_conv(
        const float* __restrict__ u,
        const float* __restrict__ gamma, const float* __restrict__ beta,
        const float* __restrict__ wd, const float* __restrict__ bd,
        const float* __restrict__ wB, const float* __restrict__ wC,
        const float* __restrict__ dtp) {
    __shared__ float ws2[2][36 * WST];   // 28.2KB
    __shared__ float xs[64 * 60];        // 15.4KB
    __shared__ float cs_scale[64], cs_shift[64];

    int bx = blockIdx.x;
    int b  = bx >> 7;
    int t  = bx & 127;
    int y0 = (t >> 4) * 8;
    int x0 = (t & 15) * 4;

    int tid = threadIdx.x;
    int ocg = tid >> 3;
    int pxg = tid & 7;
    int oc0 = ocg * 6;
    int py0 = (pxg >> 1) * 2;
    int px0 = (pxg & 1) * 2;

    if (tid < 64) {
        int bg = b * 4 + (tid >> 4);
        float S = 0.f, S2 = 0.f;
        #pragma unroll
        for (int i = 0; i < 16; i++) {
            S  += g_part[(bg * 16 + i) * 2];
            S2 += g_part[(bg * 16 + i) * 2 + 1];
        }
        float mu  = S  * (1.f / 65536.f);
        float var = S2 * (1.f / 65536.f) - mu * mu;
        float rs = rsqrtf(var + 1e-5f) * gamma[tid];
        cs_scale[tid] = rs;
        cs_shift[tid] = beta[tid] - mu * rs;
    }
    __syncthreads();

    int l_oc[7], l_rem[7];
    #pragma unroll
    for (int s = 0; s < 7; s++) {
        int l4 = tid + 128 * s;
        l_oc[s]  = l4 / 9;
        l_rem[s] = l4 - l_oc[s] * 9;
    }
    float4 rg[7];

    #pragma unroll
    for (int s = 0; s < 7; s++) {
        if (tid + 128 * s < 864) {
            int oc = l_oc[s], rem = l_rem[s];
            const float4* src;
            if (oc < 64)      src = (const float4*)wd + oc * 144 + rem;
            else if (oc < 80) src = (const float4*)wB + (oc - 64) * 144 + rem;
            else              src = (const float4*)wC + (oc - 80) * 144 + rem;
            rg[s] = __ldg(src);
        }
    }

    #pragma unroll 1
    for (int l = tid; l < 3840; l += 128) {
        int icl = l / 60; int r = l - icl * 60;
        int yy = r / 6, xx = r - yy * 6;
        int gy = (y0 + yy - 1) & 63;
        int gx = (x0 + xx - 1) & 63;
        float v = u[((b * 64 + icl) * 64 + gy) * 64 + gx];
        xs[l] = fmaf(v, cs_scale[icl], cs_shift[icl]);
    }

    #pragma unroll
    for (int s = 0; s < 7; s++) {
        if (tid + 128 * s < 864) {
            int oc = l_oc[s], rem = l_rem[s];
            ws2[0][(rem * 4 + 0) * WST + oc] = rg[s].x;
            ws2[0][(rem * 4 + 1) * WST + oc] = rg[s].y;
            ws2[0][(rem * 4 + 2) * WST + oc] = rg[s].z;
            ws2[0][(rem * 4 + 3) * WST + oc] = rg[s].w;
        }
    }
    __syncthreads();

    ull acc[3][4];
    #pragma unroll
    for (int p = 0; p < 3; p++)
        #pragma unroll
        for (int q = 0; q < 4; q++) acc[p][q] = 0ull;

    #pragma unroll 1
    for (int c = 0; c < 16; c++) {
        if (c < 15) {
            int nc = c + 1;
            #pragma unroll
            for (int s = 0; s < 7; s++) {
                if (tid + 128 * s < 864) {
                    int oc = l_oc[s], rem = l_rem[s];
                    const float4* src;
                    if (oc < 64)      src = (const float4*)wd + oc * 144 + nc * 9 + rem;
                    else if (oc < 80) src = (const float4*)wB + (oc - 64) * 144 + nc * 9 + rem;
                    else              src = (const float4*)wC + (oc - 80) * 144 + nc * 9 + rem;
                    rg[s] = __ldg(src);
                }
            }
        }

        const float* wsb = ws2[c & 1];
        #pragma unroll
        for (int icl = 0; icl < 4; icl++) {
            int ic = c * 4 + icl;
            const float* xp = xs + ic * 60 + py0 * 6 + px0;
            float xr[4][4];
            #pragma unroll
            for (int rr = 0; rr < 4; rr++) {
                float2 lo = *(const float2*)(xp + rr * 6);
                float2 hi = *(const float2*)(xp + rr * 6 + 2);
                xr[rr][0] = lo.x; xr[rr][1] = lo.y;
                xr[rr][2] = hi.x; xr[rr][3] = hi.y;
            }
            #pragma unroll
            for (int dy = 0; dy < 3; dy++) {
                #pragma unroll
                for (int dx = 0; dx < 3; dx++) {
                    const float* row = wsb + (icl * 9 + dy * 3 + dx) * WST + oc0;
                    ull w01 = *(const ull*)(row);
                    ull w23 = *(const ull*)(row + 2);
                    ull w45 = *(const ull*)(row + 4);
                    ull pa = pk2(xr[dy][dx]);
                    ull pb = pk2(xr[dy][dx + 1]);
                    ull pc = pk2(xr[dy + 1][dx]);
                    ull pd = pk2(xr[dy + 1][dx + 1]);
                    fma2(acc[0][0], w01, pa); fma2(acc[0][1], w01, pb);
                    fma2(acc[0][2], w01, pc); fma2(acc[0][3], w01, pd);
                    fma2(acc[1][0], w23, pa); fma2(acc[1][1], w23, pb);
                    fma2(acc[1][2], w23, pc); fma2(acc[1][3], w23, pd);
                    fma2(acc[2][0], w45, pa); fma2(acc[2][1], w45, pb);
                    fma2(acc[2][2], w45, pc); fma2(acc[2][3], w45, pd);
                }
            }
        }

        if (c < 15) {
            float* dstb = ws2[(c + 1) & 1];
            #pragma unroll
            for (int s = 0; s < 7; s++) {
                if (tid + 128 * s < 864) {
                    int oc = l_oc[s], rem = l_rem[s];
                    dstb[(rem * 4 + 0) * WST + oc] = rg[s].x;
                    dstb[(rem * 4 + 1) * WST + oc] = rg[s].y;
                    dstb[(rem * 4 + 2) * WST + oc] = rg[s].z;
                    dstb[(rem * 4 + 3) * WST + oc] = rg[s].w;
                }
            }
        }
        __syncthreads();
    }

    float dtv = __ldg(dtp);
    int yb = y0 + py0, xb = x0 + px0;
    int pix[4] = { yb * 64 + xb, yb * 64 + xb + 1,
                   (yb + 1) * 64 + xb, (yb + 1) * 64 + xb + 1 };

    #pragma unroll
    for (int p = 0; p < 3; p++) {
        #pragma unroll
        for (int half = 0; half < 2; half++) {
            int oc = oc0 + 2 * p + half;
            float av[4];
            #pragma unroll
            for (int q = 0; q < 4; q++) {
                float2 v = up2(acc[p][q]);
                av[q] = half ? v.y : v.x;
            }
            if (oc < 64) {
                float bias = bd[oc] + dtv;
                float* dst = g_delta + (b * 64 + oc) * HW;
                #pragma unroll
                for (int q = 0; q < 4; q++) {
                    float v = av[q] + bias;
                    float sp = (v > 0.f) ? (v + log1pf(expf(-v))) : log1pf(expf(v));
                    sp = fminf(fmaxf(sp, 1e-4f), 5.0f);
                    dst[pix[q]] = sp;
                }
            } else if (oc < 80) {
                float* dst = g_Bval + (b * 16 + (oc - 64)) * HW;
                #pragma unroll
                for (int q = 0; q < 4; q++) dst[pix[q]] = av[q];
            } else {
                float* dst = g_Cval + (b * 16 + (oc - 80)) * HW;
                #pragma unroll
                for (int q = 0; q < 4; q++) dst[pix[q]] = av[q];
            }
        }
    }
}

// ---------------------------------------------------------------------------
// K3: circulant matmuls, single X copy (18KB smem -> 5 blocks/SM).
// Phase1 (Gx): 4x8 tile; X row-pairs from Xs via 2x LDS.64 + pack; h scalar+pk2.
// Phase2 (Gy): 8x4 tile; X rows via aligned LDS.64; h scalar+pk2;
//              A_bar recomputed from delta (L2-resident).
// ---------------------------------------------------------------------------
__global__ void __launch_bounds__(128, 5) k_update(
        const float* __restrict__ u, const float* __restrict__ sprev,
        const float* __restrict__ logA, float* __restrict__ out) {
    __shared__ float Xs[64 * 68];    // X[r][c] at r*68 + c + 2*(c>>5)
    __shared__ float hb[144];        // h[i mod 64]

    int tid = threadIdx.x;
    int bp  = blockIdx.x;            // b*1024 + d*16 + n
    int b = bp >> 10, d = (bp >> 4) & 63, n = bp & 15;

    int p0 = (((b * 3 + 0) * 64 + d) * 16 + n) * HW;
    int p1 = p0 + 64 * 16 * HW;
    int p2 = p1 + 64 * 16 * HW;
    const float4* m0p4 = (const float4*)(sprev + p0);

    #pragma unroll
    for (int s = 0; s < 8; s++) {
        int l4 = tid + 128 * s;              // < 1024
        float4 v = m0p4[l4];
        int idx = l4 * 4;
        int r = idx >> 6, cc = idx & 63;
        float* xsp = &Xs[r * 68 + cc + 2 * (cc >> 5)];
        *(float2*)xsp       = make_float2(v.x, v.y);
        *(float2*)(xsp + 2) = make_float2(v.z, v.w);
    }
    for (int i = tid; i < 144; i += 128) hb[i] = g_h[i & 63];
    __syncthreads();

    float Ad = -expf(__ldg(&logA[d * 16 + n]));
    int off_bd = (b * 64 + d) * HW;
    int off_bn = (b * 16 + n) * HW;
    const int so = NB * DM * HW;

    // ===== Phase 1: Gx[r][c] = sum_k X[r][k] h[c-k], 4 rows x 8 cols =====
    {
        int rg = tid >> 3, cg = tid & 7;    // rg 0..15, cg 0..7
        int r0 = rg * 4, c0 = cg * 8;
        int gap2 = 2 * (c0 >> 5);

        ull a[2][8];
        #pragma unroll
        for (int p = 0; p < 2; p++)
            #pragma unroll
            for (int j = 0; j < 8; j++) a[p][j] = 0ull;

        #pragma unroll 1
        for (int k8 = 0; k8 < 64; k8 += 8) {
            ull hl[15];
            int hbase = c0 - k8 + 57;       // in [1,113]
            #pragma unroll
            for (int m = 0; m < 15; m++) hl[m] = pk2(hb[hbase + m]);
            int gk = 2 * (k8 >> 5);
            #pragma unroll
            for (int kk2 = 0; kk2 < 4; kk2++) {
                int xo = k8 + kk2 * 2 + gk;     // even, no gap crossing
                float2 xr0 = *(const float2*)&Xs[(r0 + 0) * 68 + xo];
                float2 xr1 = *(const float2*)&Xs[(r0 + 1) * 68 + xo];
                float2 xr2 = *(const float2*)&Xs[(r0 + 2) * 68 + xo];
                float2 xr3 = *(const float2*)&Xs[(r0 + 3) * 68 + xo];
                {   // kk = 2*kk2
                    int kk = kk2 * 2;
                    ull x01 = pk(xr0.x, xr1.x), x23 = pk(xr2.x, xr3.x);
                    #pragma unroll
                    for (int j = 0; j < 8; j++) {
                        fma2(a[0][j], x01, hl[j - kk + 7]);
                        fma2(a[1][j], x23, hl[j - kk + 7]);
                    }
                }
                {   // kk = 2*kk2+1
                    int kk = kk2 * 2 + 1;
                    ull x01 = pk(xr0.y, xr1.y), x23 = pk(xr2.y, xr3.y);
                    #pragma unroll
                    for (int j = 0; j < 8; j++) {
                        fma2(a[0][j], x01, hl[j - kk + 7]);
                        fma2(a[1][j], x23, hl[j - kk + 7]);
                    }
                }
            }
        }

        // epilogue: m0_new, mx_new
        #pragma unroll
        for (int i = 0; i < 4; i++) {
            int row = r0 + i;
            int off = row * 64 + c0;
            float4 dv0 = *(const float4*)(g_delta + off_bd + off);
            float4 dv1 = *(const float4*)(g_delta + off_bd + off + 4);
            float4 uv0 = *(const float4*)(u + off_bd + off);
            float4 uv1 = *(const float4*)(u + off_bd + off + 4);
            float4 bv0 = *(const float4*)(g_Bval + off_bn + off);
            float4 bv1 = *(const float4*)(g_Bval + off_bn + off + 4);
            float4 mx0 = *(const float4*)(sprev + p1 + off);
            float4 mx1 = *(const float4*)(sprev + p1 + off + 4);
            float dd[8] = { dv0.x, dv0.y, dv0.z, dv0.w, dv1.x, dv1.y, dv1.z, dv1.w };
            float uu[8] = { uv0.x, uv0.y, uv0.z, uv0.w, uv1.x, uv1.y, uv1.z, uv1.w };
            float bb[8] = { bv0.x, bv0.y, bv0.z, bv0.w, bv1.x, bv1.y, bv1.z, bv1.w };
            float mx[8] = { mx0.x, mx0.y, mx0.z, mx0.w, mx1.x, mx1.y, mx1.z, mx1.w };
            float m0n[8], mxn[8];
            #pragma unroll
            for (int j = 0; j < 8; j++) {
                float2 tt = up2(a[i >> 1][j]);
                float gx = (i & 1) ? tt.y : tt.x;
                float m0v = Xs[row * 68 + c0 + j + gap2];
                float Ab = __expf(dd[j] * Ad);
                m0n[j] = fmaf(Ab, m0v, dd[j] * bb[j] * uu[j]);
                mxn[j] = Ab * (mx[j] - gx);
            }
            *(float4*)(out + so + p0 + off)     = make_float4(m0n[0], m0n[1], m0n[2], m0n[3]);
            *(float4*)(out + so + p0 + off + 4) = make_float4(m0n[4], m0n[5], m0n[6], m0n[7]);
            *(float4*)(out + so + p1 + off)     = make_float4(mxn[0], mxn[1], mxn[2], mxn[3]);
            *(float4*)(out + so + p1 + off + 4) = make_float4(mxn[4], mxn[5], mxn[6], mxn[7]);
        }
    }

    // ===== Phase 2: Gy[r][c] = sum_k h[r-k] X[k][c], 8 rows x 4 cols =====
    {
        int rg2 = tid >> 4, cg2 = tid & 15;   // rg2 0..7, cg2 0..15
        int r0 = rg2 * 8, c0 = cg2 * 4;
        int gapc = 2 * (c0 >> 5);

        ull g2[8][2];
        #pragma unroll
        for (int i = 0; i < 8; i++) { g2[i][0] = 0ull; g2[i][1] = 0ull; }

        #pragma unroll 1
        for (int k8 = 0; k8 < 64; k8 += 8) {
            ull gl[15];
            int gb = r0 - k8 + 57;            // in [1,120]
            #pragma unroll
            for (int m = 0; m < 15; m++) gl[m] = pk2(hb[gb + m]);
            #pragma unroll
            for (int kk = 0; kk < 8; kk++) {
                int ro = (k8 + kk) * 68 + c0 + gapc;   // even -> 8B aligned
                ull xq0 = *(const ull*)&Xs[ro];
                ull xq1 = *(const ull*)&Xs[ro + 2];
                #pragma unroll
                for (int i = 0; i < 8; i++) {
                    fma2(g2[i][0], gl[i - kk + 7], xq0);
                    fma2(g2[i][1], gl[i - kk + 7], xq1);
                }
            }
        }

        // epilogue: my_new (A_bar recomputed; delta tile is L2-resident)
        #pragma unroll
        for (int i = 0; i < 8; i++) {
            int row = r0 + i;
            int off = row * 64 + c0;
            float4 dv = *(const float4*)(g_delta + off_bd + off);
            float4 my = *(const float4*)(sprev + p2 + off);
            float2 t0 = up2(g2[i][0]);
            float2 t1 = up2(g2[i][1]);
            float4 myn;
            myn.x = __expf(dv.x * Ad) * (my.x - t0.x);
            myn.y = __expf(dv.y * Ad) * (my.y - t0.y);
            myn.z = __expf(dv.z * Ad) * (my.z - t1.x);
            myn.w = __expf(dv.w * Ad) * (my.w - t1.y);
            *(float4*)(out + so + p2 + off) = myn;
        }
    }
}

// ---------------------------------------------------------------------------
// K4: y[b,d,p] = sum_n m0_new[b,d,n,p] * C_val[b,n,p] + u*D[d]  (float4)
// ---------------------------------------------------------------------------
__global__ void k_y(const float* __restrict__ u, const float* __restrict__ Dp,
                    float* __restrict__ out) {
    int idx4 = blockIdx.x * 256 + threadIdx.x;   // < 262144
    int b = idx4 >> 16;
    int d = (idx4 >> 10) & 63;
    int p4 = idx4 & 1023;
    const int so = NB * DM * HW;
    const float4* m0n = (const float4*)(out + so + ((b * 3 * 64 + d) * 16) * HW) + p4;
    const float4* Cv  = (const float4*)(g_Cval + (b * 16) * HW) + p4;
    float4 a = make_float4(0.f, 0.f, 0.f, 0.f);
    #pragma unroll
    for (int nn = 0; nn < 16; nn++) {
        float4 m = m0n[nn * 1024];
        float4 c = Cv[nn * 1024];
        a.x = fmaf(m.x, c.x, a.x); a.y = fmaf(m.y, c.y, a.y);
        a.z = fmaf(m.z, c.z, a.z); a.w = fmaf(m.w, c.w, a.w);
    }
    float Dd = Dp[d];
    float4 uv = ((const float4*)u)[idx4];
    a.x = fmaf(uv.x, Dd, a.x); a.y = fmaf(uv.y, Dd, a.y);
    a.z = fmaf(uv.z, Dd, a.z); a.w = fmaf(uv.w, Dd, a.w);
    ((float4*)out)[idx4] = a;
}

// ---------------------------------------------------------------------------
extern "C" void kernel_launch(void* const* d_in, const int* in_sizes, int n_in,
                              void* d_out, int out_size) {
    const float* u     = (const float*)d_in[0];
    const float* sprev = (const float*)d_in[1];
    const float* gamma = (const float*)d_in[2];
    const float* beta  = (const float*)d_in[3];
    const float* wd    = (const float*)d_in[4];
    const float* bd    = (const float*)d_in[5];
    const float* wB    = (const float*)d_in[6];
    const float* wC    = (const float*)d_in[7];
    const float* logA  = (const float*)d_in[8];
    const float* Dp    = (const float*)d_in[9];
    const float* dt    = (const float*)d_in[10];
    float* out = (float*)d_out;

    k_init_h<<<1, 64>>>();
    k_stats<<<256, 256>>>(u);
    k_conv<<<512, 128>>>(u, gamma, beta, wd, bd, wB, wC, dt);
    k_update<<<4096, 128>>>(u, sprev, logA, out);
    k_y<<<1024, 256>>>(u, Dp, out);
}

// round 12
// speedup vs baseline: 1.2477x; 1.0661x over previous
#include <cuda_runtime.h>
#include <math.h>

#define HW    4096
#define DM    64
#define DS    16
#define NB    4

// Scratch (device globals; no allocation allowed)
__device__ float g_h[64];
__device__ float g_part[512];         // 256 blocks x (sum, sumsq)
__device__ float g_wT[16 * 3528];     // transposed weights [chunk][icl*9+tap][98]
__device__ float g_delta[NB*DM*HW];   // 4MB
__device__ float g_Bval[NB*DS*HW];    // 1MB
__device__ float g_Cval[NB*DS*HW];    // 1MB

typedef unsigned long long ull;

__device__ __forceinline__ ull pk2(float x) {
    ull r; asm("mov.b64 %0,{%1,%1};" : "=l"(r) : "f"(x)); return r;
}
__device__ __forceinline__ ull pk(float lo, float hi) {
    ull r; asm("mov.b64 %0,{%1,%2};" : "=l"(r) : "f"(lo), "f"(hi)); return r;
}
__device__ __forceinline__ void fma2(ull &a, ull b, ull c) {
    asm("fma.rn.f32x2 %0,%1,%2,%0;" : "+l"(a) : "l"(b), "l"(c));
}
__device__ __forceinline__ float2 up2(ull a) {
    float2 v; asm("mov.b64 {%0,%1},%2;" : "=f"(v.x), "=f"(v.y) : "l"(a)); return v;
}

// ---------------------------------------------------------------------------
// K0: spectral-derivative circular kernel h[n] (exact, fp64 accumulation)
// ---------------------------------------------------------------------------
__global__ void k_init_h() {
    int n = threadIdx.x;  // 0..63
    double acc = 0.0;
    for (int m = 1; m < 32; m++) {
        double km = 2.0 * 3.141592653589793238 * (double)m / 64.0;
        acc += km * sin(km * (double)n);
    }
    g_h[n] = (float)(-acc * 2.0 / 64.0);
}

// ---------------------------------------------------------------------------
// K0b: transpose conv weights -> g_wT[chunk][icl*9+tap][oc] (stride 98)
// ---------------------------------------------------------------------------
__global__ void k_wprep(const float* __restrict__ wd,
                        const float* __restrict__ wB,
                        const float* __restrict__ wC) {
    int idx = blockIdx.x * 256 + threadIdx.x;
    if (idx >= 16 * 3528) return;
    int chunk = idx / 3528;
    int r2 = idx - chunk * 3528;
    int row = r2 / 98;            // icl*9 + tap
    int oc  = r2 - row * 98;
    int icl = row / 9, tap = row - icl * 9;
    int ic  = chunk * 4 + icl;
    float v = 0.f;
    if (oc < 64)      v = wd[oc * 576 + ic * 9 + tap];
    else if (oc < 80) v = wB[(oc - 64) * 576 + ic * 9 + tap];
    else if (oc < 96) v = wC[(oc - 80) * 576 + ic * 9 + tap];
    g_wT[idx] = v;
}

// ---------------------------------------------------------------------------
// K1: GroupNorm partial sums. 256 blocks (16 per (b,g)), deterministic.
// ---------------------------------------------------------------------------
__global__ void __launch_bounds__(256) k_stats(const float* __restrict__ u) {
    int blk = blockIdx.x;
    int bg = blk >> 4, seg = blk & 15;
    const float4* base = (const float4*)(u + bg * 65536 + seg * 4096);
    float s = 0.f, s2 = 0.f;
    #pragma unroll
    for (int i = threadIdx.x; i < 1024; i += 256) {
        float4 v = base[i];
        s += v.x + v.y + v.z + v.w;
        s2 = fmaf(v.x, v.x, s2); s2 = fmaf(v.y, v.y, s2);
        s2 = fmaf(v.z, v.z, s2); s2 = fmaf(v.w, v.w, s2);
    }
    for (int o = 16; o; o >>= 1) {
        s  += __shfl_down_sync(0xFFFFFFFFu, s,  o);
        s2 += __shfl_down_sync(0xFFFFFFFFu, s2, o);
    }
    __shared__ float ss[8], ss2[8];
    int w = threadIdx.x >> 5, l = threadIdx.x & 31;
    if (l == 0) { ss[w] = s; ss2[w] = s2; }
    __syncthreads();
    if (threadIdx.x == 0) {
        float S = 0.f, S2 = 0.f;
        #pragma unroll
        for (int i = 0; i < 8; i++) { S += ss[i]; S2 += ss2[i]; }
        g_part[blk * 2]     = S;
        g_part[blk * 2 + 1] = S2;
    }
}

// ---------------------------------------------------------------------------
// K2 v2: fused GroupNorm + circular 3x3 convs.
// Grid 512 = 4b x 64 rows x 2 col-halves. Tile = 1 row x 32 cols, all 96 oc.
// Weights cp.async'd from pre-transposed g_wT (double-buffered).
// Halo: 12 rows x 34 contiguous cols per chunk (coalesced), double-buffered.
// Thread = 6 oc x 4 px (f32x2 over oc pairs). One barrier per chunk.
// ---------------------------------------------------------------------------
__global__ void __launch_bounds__(128, 4) k_conv(
        const float* __restrict__ u,
        const float* __restrict__ gamma, const float* __restrict__ beta,
        const float* __restrict__ bd, const float* __restrict__ dtp) {
    __shared__ float ws2[2][3528];       // 28.2KB [buf][(icl*9+tap)*98 + oc]
    __shared__ float xs2[2][408];        // 3.3KB  [buf][(icl*3+rr)*34 + j]
    __shared__ float cs_scale[64], cs_shift[64];

    int bx = blockIdx.x;
    int b  = bx >> 7;
    int t  = bx & 127;
    int y  = t >> 1;
    int x0 = (t & 1) * 32;

    int tid = threadIdx.x;
    int ocg = tid >> 3;            // 0..15
    int pxg = tid & 7;             // 0..7
    int oc0 = ocg * 6;
    int px0 = pxg * 4;

    // finalize GroupNorm stats from partials
    if (tid < 64) {
        int bg = b * 4 + (tid >> 4);
        float S = 0.f, S2 = 0.f;
        #pragma unroll
        for (int i = 0; i < 16; i++) {
            S  += g_part[(bg * 16 + i) * 2];
            S2 += g_part[(bg * 16 + i) * 2 + 1];
        }
        float mu  = S  * (1.f / 65536.f);
        float var = S2 * (1.f / 65536.f) - mu * mu;
        float rs = rsqrtf(var + 1e-5f) * gamma[tid];
        cs_scale[tid] = rs;
        cs_shift[tid] = beta[tid] - mu * rs;
    }
    __syncthreads();

    // per-thread x-load slots (chunk-invariant decomposition)
    int s_row[4], s_j[4], s_icl[4], s_gy[4], s_gx[4];
    bool s_ok[4];
    #pragma unroll
    for (int s = 0; s < 4; s++) {
        int idx = tid + 128 * s;
        s_ok[s] = idx < 408;
        int row = idx / 34;          // 0..11
        int j   = idx - row * 34;
        if (!s_ok[s]) { row = 0; j = 0; }
        int icl = row / 3;
        int rr  = row - icl * 3;
        s_row[s] = row; s_j[s] = j; s_icl[s] = icl;
        s_gy[s] = (y + rr - 1) & 63;
        s_gx[s] = (x0 - 1 + j) & 63;
    }

    unsigned ws_sm = (unsigned)__cvta_generic_to_shared(ws2);

    // issue w chunk 0 via cp.async
    {
        const float4* wsrc = (const float4*)g_wT;
        #pragma unroll
        for (int s = 0; s < 7; s++) {
            int i = tid + 128 * s;
            if (i < 882) {
                unsigned dst = ws_sm + i * 16;
                asm volatile("cp.async.cg.shared.global [%0], [%1], 16;"
                             :: "r"(dst), "l"(wsrc + i));
            }
        }
        asm volatile("cp.async.commit_group;");
    }
    // load + normalize x chunk 0, STS
    {
        #pragma unroll
        for (int s = 0; s < 4; s++) {
            if (s_ok[s]) {
                int ic = s_icl[s];
                float v = u[((b * 64 + ic) * 64 + s_gy[s]) * 64 + s_gx[s]];
                xs2[0][s_row[s] * 34 + s_j[s]] = fmaf(v, cs_scale[ic], cs_shift[ic]);
            }
        }
    }
    asm volatile("cp.async.wait_group 0;");
    __syncthreads();

    ull acc[3][4];   // oc pairs (oc0+2p, oc0+2p+1) x 4 px
    #pragma unroll
    for (int p = 0; p < 3; p++)
        #pragma unroll
        for (int q = 0; q < 4; q++) acc[p][q] = 0ull;

    #pragma unroll 1
    for (int c = 0; c < 16; c++) {
        float xstage[4];
        if (c < 15) {
            // cp.async next weight chunk into other buffer
            const float4* wsrc = (const float4*)g_wT + (c + 1) * 882;
            unsigned wdst = ws_sm + ((c + 1) & 1) * 14112;
            #pragma unroll
            for (int s = 0; s < 7; s++) {
                int i = tid + 128 * s;
                if (i < 882) {
                    asm volatile("cp.async.cg.shared.global [%0], [%1], 16;"
                                 :: "r"(wdst + i * 16), "l"(wsrc + i));
                }
            }
            asm volatile("cp.async.commit_group;");
            // LDG next x chunk (coalesced rows)
            #pragma unroll
            for (int s = 0; s < 4; s++) {
                if (s_ok[s]) {
                    int ic = (c + 1) * 4 + s_icl[s];
                    float v = u[((b * 64 + ic) * 64 + s_gy[s]) * 64 + s_gx[s]];
                    xstage[s] = fmaf(v, cs_scale[ic], cs_shift[ic]);
                }
            }
        }

        // compute chunk c
        const float* wsb = ws2[c & 1];
        const float* xsb = xs2[c & 1];
        #pragma unroll
        for (int icl = 0; icl < 4; icl++) {
            const float* xp = xsb + icl * 102 + px0;   // 3 rows of 34
            ull P[3][6];
            #pragma unroll
            for (int rr = 0; rr < 3; rr++) {
                float2 p0 = *(const float2*)(xp + rr * 34);
                float2 p1 = *(const float2*)(xp + rr * 34 + 2);
                float2 p2 = *(const float2*)(xp + rr * 34 + 4);
                P[rr][0] = pk2(p0.x); P[rr][1] = pk2(p0.y);
                P[rr][2] = pk2(p1.x); P[rr][3] = pk2(p1.y);
                P[rr][4] = pk2(p2.x); P[rr][5] = pk2(p2.y);
            }
            #pragma unroll
            for (int dy = 0; dy < 3; dy++) {
                #pragma unroll
                for (int dx = 0; dx < 3; dx++) {
                    const float* row = wsb + (icl * 9 + dy * 3 + dx) * 98 + oc0;
                    ull w01 = *(const ull*)(row);
                    ull w23 = *(const ull*)(row + 2);
                    ull w45 = *(const ull*)(row + 4);
                    ull pa = P[dy][dx];
                    ull pb = P[dy][dx + 1];
                    ull pc = P[dy][dx + 2];
                    ull pd = P[dy][dx + 3];
                    fma2(acc[0][0], w01, pa); fma2(acc[0][1], w01, pb);
                    fma2(acc[0][2], w01, pc); fma2(acc[0][3], w01, pd);
                    fma2(acc[1][0], w23, pa); fma2(acc[1][1], w23, pb);
                    fma2(acc[1][2], w23, pc); fma2(acc[1][3], w23, pd);
                    fma2(acc[2][0], w45, pa); fma2(acc[2][1], w45, pb);
                    fma2(acc[2][2], w45, pc); fma2(acc[2][3], w45, pd);
                }
            }
        }

        if (c < 15) {
            float* xdst = xs2[(c + 1) & 1];
            #pragma unroll
            for (int s = 0; s < 4; s++)
                if (s_ok[s]) xdst[s_row[s] * 34 + s_j[s]] = xstage[s];
            asm volatile("cp.async.wait_group 0;");
        }
        __syncthreads();
    }

    // epilogue: float4 stores, softplus for delta channels
    float dtv = __ldg(dtp);
    int pbase = y * 64 + x0 + px0;

    #pragma unroll
    for (int p = 0; p < 3; p++) {
        #pragma unroll
        for (int half = 0; half < 2; half++) {
            int oc = oc0 + 2 * p + half;
            float av[4];
            #pragma unroll
            for (int q = 0; q < 4; q++) {
                float2 v = up2(acc[p][q]);
                av[q] = half ? v.y : v.x;
            }
            if (oc < 64) {
                float bias = bd[oc] + dtv;
                float4 o4;
                float* pv = &o4.x;
                #pragma unroll
                for (int q = 0; q < 4; q++) {
                    float v = av[q] + bias;
                    float sp = (v > 0.f) ? (v + log1pf(expf(-v))) : log1pf(expf(v));
                    pv[q] = fminf(fmaxf(sp, 1e-4f), 5.0f);
                }
                *(float4*)(g_delta + (b * 64 + oc) * HW + pbase) = o4;
            } else if (oc < 80) {
                *(float4*)(g_Bval + (b * 16 + (oc - 64)) * HW + pbase) =
                    make_float4(av[0], av[1], av[2], av[3]);
            } else {
                *(float4*)(g_Cval + (b * 16 + (oc - 80)) * HW + pbase) =
                    make_float4(av[0], av[1], av[2], av[3]);
            }
        }
    }
}

// ---------------------------------------------------------------------------
// K3: circulant matmuls, single X copy (18KB smem -> 5 blocks/SM).
// Phase1 (Gx): 4x8 tile; X row-pairs from Xs via 2x LDS.64 + pack; h scalar+pk2.
// Phase2 (Gy): 8x4 tile; X rows via aligned LDS.64; h scalar+pk2;
//              A_bar recomputed from delta (L2-resident).
// ---------------------------------------------------------------------------
__global__ void __launch_bounds__(128, 5) k_update(
        const float* __restrict__ u, const float* __restrict__ sprev,
        const float* __restrict__ logA, float* __restrict__ out) {
    __shared__ float Xs[64 * 68];    // X[r][c] at r*68 + c + 2*(c>>5)
    __shared__ float hb[144];        // h[i mod 64]

    int tid = threadIdx.x;
    int bp  = blockIdx.x;            // b*1024 + d*16 + n
    int b = bp >> 10, d = (bp >> 4) & 63, n = bp & 15;

    int p0 = (((b * 3 + 0) * 64 + d) * 16 + n) * HW;
    int p1 = p0 + 64 * 16 * HW;
    int p2 = p1 + 64 * 16 * HW;
    const float4* m0p4 = (const float4*)(sprev + p0);

    #pragma unroll
    for (int s = 0; s < 8; s++) {
        int l4 = tid + 128 * s;              // < 1024
        float4 v = m0p4[l4];
        int idx = l4 * 4;
        int r = idx >> 6, cc = idx & 63;
        float* xsp = &Xs[r * 68 + cc + 2 * (cc >> 5)];
        *(float2*)xsp       = make_float2(v.x, v.y);
        *(float2*)(xsp + 2) = make_float2(v.z, v.w);
    }
    for (int i = tid; i < 144; i += 128) hb[i] = g_h[i & 63];
    __syncthreads();

    float Ad = -expf(__ldg(&logA[d * 16 + n]));
    int off_bd = (b * 64 + d) * HW;
    int off_bn = (b * 16 + n) * HW;
    const int so = NB * DM * HW;

    // ===== Phase 1: Gx[r][c] = sum_k X[r][k] h[c-k], 4 rows x 8 cols =====
    {
        int rg = tid >> 3, cg = tid & 7;    // rg 0..15, cg 0..7
        int r0 = rg * 4, c0 = cg * 8;
        int gap2 = 2 * (c0 >> 5);

        ull a[2][8];
        #pragma unroll
        for (int p = 0; p < 2; p++)
            #pragma unroll
            for (int j = 0; j < 8; j++) a[p][j] = 0ull;

        #pragma unroll 1
        for (int k8 = 0; k8 < 64; k8 += 8) {
            ull hl[15];
            int hbase = c0 - k8 + 57;       // in [1,113]
            #pragma unroll
            for (int m = 0; m < 15; m++) hl[m] = pk2(hb[hbase + m]);
            int gk = 2 * (k8 >> 5);
            #pragma unroll
            for (int kk2 = 0; kk2 < 4; kk2++) {
                int xo = k8 + kk2 * 2 + gk;     // even, no gap crossing
                float2 xr0 = *(const float2*)&Xs[(r0 + 0) * 68 + xo];
                float2 xr1 = *(const float2*)&Xs[(r0 + 1) * 68 + xo];
                float2 xr2 = *(const float2*)&Xs[(r0 + 2) * 68 + xo];
                float2 xr3 = *(const float2*)&Xs[(r0 + 3) * 68 + xo];
                {   // kk = 2*kk2
                    int kk = kk2 * 2;
                    ull x01 = pk(xr0.x, xr1.x), x23 = pk(xr2.x, xr3.x);
                    #pragma unroll
                    for (int j = 0; j < 8; j++) {
                        fma2(a[0][j], x01, hl[j - kk + 7]);
                        fma2(a[1][j], x23, hl[j - kk + 7]);
                    }
                }
                {   // kk = 2*kk2+1
                    int kk = kk2 * 2 + 1;
                    ull x01 = pk(xr0.y, xr1.y), x23 = pk(xr2.y, xr3.y);
                    #pragma unroll
                    for (int j = 0; j < 8; j++) {
                        fma2(a[0][j], x01, hl[j - kk + 7]);
                        fma2(a[1][j], x23, hl[j - kk + 7]);
                    }
                }
            }
        }

        // epilogue: m0_new, mx_new
        #pragma unroll
        for (int i = 0; i < 4; i++) {
            int row = r0 + i;
            int off = row * 64 + c0;
            float4 dv0 = *(const float4*)(g_delta + off_bd + off);
            float4 dv1 = *(const float4*)(g_delta + off_bd + off + 4);
            float4 uv0 = *(const float4*)(u + off_bd + off);
            float4 uv1 = *(const float4*)(u + off_bd + off + 4);
            float4 bv0 = *(const float4*)(g_Bval + off_bn + off);
            float4 bv1 = *(const float4*)(g_Bval + off_bn + off + 4);
            float4 mx0 = *(const float4*)(sprev + p1 + off);
            float4 mx1 = *(const float4*)(sprev + p1 + off + 4);
            float dd[8] = { dv0.x, dv0.y, dv0.z, dv0.w, dv1.x, dv1.y, dv1.z, dv1.w };
            float uu[8] = { uv0.x, uv0.y, uv0.z, uv0.w, uv1.x, uv1.y, uv1.z, uv1.w };
            float bb[8] = { bv0.x, bv0.y, bv0.z, bv0.w, bv1.x, bv1.y, bv1.z, bv1.w };
            float mx[8] = { mx0.x, mx0.y, mx0.z, mx0.w, mx1.x, mx1.y, mx1.z, mx1.w };
            float m0n[8], mxn[8];
            #pragma unroll
            for (int j = 0; j < 8; j++) {
                float2 tt = up2(a[i >> 1][j]);
                float gx = (i & 1) ? tt.y : tt.x;
                float m0v = Xs[row * 68 + c0 + j + gap2];
                float Ab = __expf(dd[j] * Ad);
                m0n[j] = fmaf(Ab, m0v, dd[j] * bb[j] * uu[j]);
                mxn[j] = Ab * (mx[j] - gx);
            }
            *(float4*)(out + so + p0 + off)     = make_float4(m0n[0], m0n[1], m0n[2], m0n[3]);
            *(float4*)(out + so + p0 + off + 4) = make_float4(m0n[4], m0n[5], m0n[6], m0n[7]);
            *(float4*)(out + so + p1 + off)     = make_float4(mxn[0], mxn[1], mxn[2], mxn[3]);
            *(float4*)(out + so + p1 + off + 4) = make_float4(mxn[4], mxn[5], mxn[6], mxn[7]);
        }
    }

    // ===== Phase 2: Gy[r][c] = sum_k h[r-k] X[k][c], 8 rows x 4 cols =====
    {
        int rg2 = tid >> 4, cg2 = tid & 15;   // rg2 0..7, cg2 0..15
        int r0 = rg2 * 8, c0 = cg2 * 4;
        int gapc = 2 * (c0 >> 5);

        ull g2[8][2];
        #pragma unroll
        for (int i = 0; i < 8; i++) { g2[i][0] = 0ull; g2[i][1] = 0ull; }

        #pragma unroll 1
        for (int k8 = 0; k8 < 64; k8 += 8) {
            ull gl[15];
            int gb = r0 - k8 + 57;            // in [1,120]
            #pragma unroll
            for (int m = 0; m < 15; m++) gl[m] = pk2(hb[gb + m]);
            #pragma unroll
            for (int kk = 0; kk < 8; kk++) {
                int ro = (k8 + kk) * 68 + c0 + gapc;   // even -> 8B aligned
                ull xq0 = *(const ull*)&Xs[ro];
                ull xq1 = *(const ull*)&Xs[ro + 2];
                #pragma unroll
                for (int i = 0; i < 8; i++) {
                    fma2(g2[i][0], gl[i - kk + 7], xq0);
                    fma2(g2[i][1], gl[i - kk + 7], xq1);
                }
            }
        }

        // epilogue: my_new (A_bar recomputed; delta tile is L2-resident)
        #pragma unroll
        for (int i = 0; i < 8; i++) {
            int row = r0 + i;
            int off = row * 64 + c0;
            float4 dv = *(const float4*)(g_delta + off_bd + off);
            float4 my = *(const float4*)(sprev + p2 + off);
            float2 t0 = up2(g2[i][0]);
            float2 t1 = up2(g2[i][1]);
            float4 myn;
            myn.x = __expf(dv.x * Ad) * (my.x - t0.x);
            myn.y = __expf(dv.y * Ad) * (my.y - t0.y);
            myn.z = __expf(dv.z * Ad) * (my.z - t1.x);
            myn.w = __expf(dv.w * Ad) * (my.w - t1.y);
            *(float4*)(out + so + p2 + off) = myn;
        }
    }
}

// ---------------------------------------------------------------------------
// K4: y[b,d,p] = sum_n m0_new[b,d,n,p] * C_val[b,n,p] + u*D[d]  (float4)
// ---------------------------------------------------------------------------
__global__ void k_y(const float* __restrict__ u, const float* __restrict__ Dp,
                    float* __restrict__ out) {
    int idx4 = blockIdx.x * 256 + threadIdx.x;   // < 262144
    int b = idx4 >> 16;
    int d = (idx4 >> 10) & 63;
    int p4 = idx4 & 1023;
    const int so = NB * DM * HW;
    const float4* m0n = (const float4*)(out + so + ((b * 3 * 64 + d) * 16) * HW) + p4;
    const float4* Cv  = (const float4*)(g_Cval + (b * 16) * HW) + p4;
    float4 a = make_float4(0.f, 0.f, 0.f, 0.f);
    #pragma unroll
    for (int nn = 0; nn < 16; nn++) {
        float4 m = m0n[nn * 1024];
        float4 c = Cv[nn * 1024];
        a.x = fmaf(m.x, c.x, a.x); a.y = fmaf(m.y, c.y, a.y);
        a.z = fmaf(m.z, c.z, a.z); a.w = fmaf(m.w, c.w, a.w);
    }
    float Dd = Dp[d];
    float4 uv = ((const float4*)u)[idx4];
    a.x = fmaf(uv.x, Dd, a.x); a.y = fmaf(uv.y, Dd, a.y);
    a.z = fmaf(uv.z, Dd, a.z); a.w = fmaf(uv.w, Dd, a.w);
    ((float4*)out)[idx4] = a;
}

// ---------------------------------------------------------------------------
extern "C" void kernel_launch(void* const* d_in, const int* in_sizes, int n_in,
                              void* d_out, int out_size) {
    const float* u     = (const float*)d_in[0];
    const float* sprev = (const float*)d_in[1];
    const float* gamma = (const float*)d_in[2];
    const float* beta  = (const float*)d_in[3];
    const float* wd    = (const float*)d_in[4];
    const float* bd    = (const float*)d_in[5];
    const float* wB    = (const float*)d_in[6];
    const float* wC    = (const float*)d_in[7];
    const float* logA  = (const float*)d_in[8];
    const float* Dp    = (const float*)d_in[9];
    const float* dt    = (const float*)d_in[10];
    float* out = (float*)d_out;

    k_init_h<<<1, 64>>>();
    k_wprep<<<221, 256>>>(wd, wB, wC);
    k_stats<<<256, 256>>>(u);
    k_conv<<<512, 128>>>(u, gamma, beta, bd, dt);
    k_update<<<4096, 128>>>(u, sprev, logA, out);
    k_y<<<1024, 256>>>(u, Dp, out);
}

// round 13
// speedup vs baseline: 1.2972x; 1.0397x over previous
#include <cuda_runtime.h>
#include <math.h>

#define HW    4096
#define DM    64
#define DS    16
#define NB    4

// Scratch (device globals; no allocation allowed)
__device__ float g_h[64];
__device__ float g_part[512];         // 256 blocks x (sum, sumsq)
__device__ float g_wT[16 * 3528];     // transposed weights [chunk][icl*9+tap][98]
__device__ float g_delta[NB*DM*HW];   // 4MB
__device__ float g_Bval[NB*DS*HW];    // 1MB
__device__ float g_Cval[NB*DS*HW];    // 1MB

typedef unsigned long long ull;

__device__ __forceinline__ ull pk2(float x) {
    ull r; asm("mov.b64 %0,{%1,%1};" : "=l"(r) : "f"(x)); return r;
}
__device__ __forceinline__ ull pk(float lo, float hi) {
    ull r; asm("mov.b64 %0,{%1,%2};" : "=l"(r) : "f"(lo), "f"(hi)); return r;
}
__device__ __forceinline__ void fma2(ull &a, ull b, ull c) {
    asm("fma.rn.f32x2 %0,%1,%2,%0;" : "+l"(a) : "l"(b), "l"(c));
}
__device__ __forceinline__ float2 up2(ull a) {
    float2 v; asm("mov.b64 {%0,%1},%2;" : "=f"(v.x), "=f"(v.y) : "l"(a)); return v;
}

// ---------------------------------------------------------------------------
// K0: weight transpose -> g_wT, plus spectral kernel h (block 0).
// ---------------------------------------------------------------------------
__global__ void k_wprep(const float* __restrict__ wd,
                        const float* __restrict__ wB,
                        const float* __restrict__ wC) {
    if (blockIdx.x == 0 && threadIdx.x < 64) {
        int n = threadIdx.x;
        double acc = 0.0;
        for (int m = 1; m < 32; m++) {
            double km = 2.0 * 3.141592653589793238 * (double)m / 64.0;
            acc += km * sin(km * (double)n);
        }
        g_h[n] = (float)(-acc * 2.0 / 64.0);
    }
    int idx = blockIdx.x * 256 + threadIdx.x;
    if (idx >= 16 * 3528) return;
    int chunk = idx / 3528;
    int r2 = idx - chunk * 3528;
    int row = r2 / 98;            // icl*9 + tap
    int oc  = r2 - row * 98;
    int icl = row / 9, tap = row - icl * 9;
    int ic  = chunk * 4 + icl;
    float v = 0.f;
    if (oc < 64)      v = wd[oc * 576 + ic * 9 + tap];
    else if (oc < 80) v = wB[(oc - 64) * 576 + ic * 9 + tap];
    else if (oc < 96) v = wC[(oc - 80) * 576 + ic * 9 + tap];
    g_wT[idx] = v;
}

// ---------------------------------------------------------------------------
// K1: GroupNorm partial sums. 256 blocks (16 per (b,g)), deterministic.
// ---------------------------------------------------------------------------
__global__ void __launch_bounds__(256) k_stats(const float* __restrict__ u) {
    int blk = blockIdx.x;
    int bg = blk >> 4, seg = blk & 15;
    const float4* base = (const float4*)(u + bg * 65536 + seg * 4096);
    float s = 0.f, s2 = 0.f;
    #pragma unroll
    for (int i = threadIdx.x; i < 1024; i += 256) {
        float4 v = base[i];
        s += v.x + v.y + v.z + v.w;
        s2 = fmaf(v.x, v.x, s2); s2 = fmaf(v.y, v.y, s2);
        s2 = fmaf(v.z, v.z, s2); s2 = fmaf(v.w, v.w, s2);
    }
    for (int o = 16; o; o >>= 1) {
        s  += __shfl_down_sync(0xFFFFFFFFu, s,  o);
        s2 += __shfl_down_sync(0xFFFFFFFFu, s2, o);
    }
    __shared__ float ss[8], ss2[8];
    int w = threadIdx.x >> 5, l = threadIdx.x & 31;
    if (l == 0) { ss[w] = s; ss2[w] = s2; }
    __syncthreads();
    if (threadIdx.x == 0) {
        float S = 0.f, S2 = 0.f;
        #pragma unroll
        for (int i = 0; i < 8; i++) { S += ss[i]; S2 += ss2[i]; }
        g_part[blk * 2]     = S;
        g_part[blk * 2 + 1] = S2;
    }
}

// ---------------------------------------------------------------------------
// K2: fused GroupNorm + circular 3x3 convs (unchanged from R12).
// ---------------------------------------------------------------------------
__global__ void __launch_bounds__(128, 4) k_conv(
        const float* __restrict__ u,
        const float* __restrict__ gamma, const float* __restrict__ beta,
        const float* __restrict__ bd, const float* __restrict__ dtp) {
    __shared__ float ws2[2][3528];       // 28.2KB [buf][(icl*9+tap)*98 + oc]
    __shared__ float xs2[2][408];        // 3.3KB  [buf][(icl*3+rr)*34 + j]
    __shared__ float cs_scale[64], cs_shift[64];

    int bx = blockIdx.x;
    int b  = bx >> 7;
    int t  = bx & 127;
    int y  = t >> 1;
    int x0 = (t & 1) * 32;

    int tid = threadIdx.x;
    int ocg = tid >> 3;            // 0..15
    int pxg = tid & 7;             // 0..7
    int oc0 = ocg * 6;
    int px0 = pxg * 4;

    if (tid < 64) {
        int bg = b * 4 + (tid >> 4);
        float S = 0.f, S2 = 0.f;
        #pragma unroll
        for (int i = 0; i < 16; i++) {
            S  += g_part[(bg * 16 + i) * 2];
            S2 += g_part[(bg * 16 + i) * 2 + 1];
        }
        float mu  = S  * (1.f / 65536.f);
        float var = S2 * (1.f / 65536.f) - mu * mu;
        float rs = rsqrtf(var + 1e-5f) * gamma[tid];
        cs_scale[tid] = rs;
        cs_shift[tid] = beta[tid] - mu * rs;
    }
    __syncthreads();

    int s_row[4], s_j[4], s_icl[4], s_gy[4], s_gx[4];
    bool s_ok[4];
    #pragma unroll
    for (int s = 0; s < 4; s++) {
        int idx = tid + 128 * s;
        s_ok[s] = idx < 408;
        int row = idx / 34;
        int j   = idx - row * 34;
        if (!s_ok[s]) { row = 0; j = 0; }
        int icl = row / 3;
        int rr  = row - icl * 3;
        s_row[s] = row; s_j[s] = j; s_icl[s] = icl;
        s_gy[s] = (y + rr - 1) & 63;
        s_gx[s] = (x0 - 1 + j) & 63;
    }

    unsigned ws_sm = (unsigned)__cvta_generic_to_shared(ws2);

    {
        const float4* wsrc = (const float4*)g_wT;
        #pragma unroll
        for (int s = 0; s < 7; s++) {
            int i = tid + 128 * s;
            if (i < 882) {
                unsigned dst = ws_sm + i * 16;
                asm volatile("cp.async.cg.shared.global [%0], [%1], 16;"
                             :: "r"(dst), "l"(wsrc + i));
            }
        }
        asm volatile("cp.async.commit_group;");
    }
    {
        #pragma unroll
        for (int s = 0; s < 4; s++) {
            if (s_ok[s]) {
                int ic = s_icl[s];
                float v = u[((b * 64 + ic) * 64 + s_gy[s]) * 64 + s_gx[s]];
                xs2[0][s_row[s] * 34 + s_j[s]] = fmaf(v, cs_scale[ic], cs_shift[ic]);
            }
        }
    }
    asm volatile("cp.async.wait_group 0;");
    __syncthreads();

    ull acc[3][4];
    #pragma unroll
    for (int p = 0; p < 3; p++)
        #pragma unroll
        for (int q = 0; q < 4; q++) acc[p][q] = 0ull;

    #pragma unroll 1
    for (int c = 0; c < 16; c++) {
        float xstage[4];
        if (c < 15) {
            const float4* wsrc = (const float4*)g_wT + (c + 1) * 882;
            unsigned wdst = ws_sm + ((c + 1) & 1) * 14112;
            #pragma unroll
            for (int s = 0; s < 7; s++) {
                int i = tid + 128 * s;
                if (i < 882) {
                    asm volatile("cp.async.cg.shared.global [%0], [%1], 16;"
                                 :: "r"(wdst + i * 16), "l"(wsrc + i));
                }
            }
            asm volatile("cp.async.commit_group;");
            #pragma unroll
            for (int s = 0; s < 4; s++) {
                if (s_ok[s]) {
                    int ic = (c + 1) * 4 + s_icl[s];
                    float v = u[((b * 64 + ic) * 64 + s_gy[s]) * 64 + s_gx[s]];
                    xstage[s] = fmaf(v, cs_scale[ic], cs_shift[ic]);
                }
            }
        }

        const float* wsb = ws2[c & 1];
        const float* xsb = xs2[c & 1];
        #pragma unroll
        for (int icl = 0; icl < 4; icl++) {
            const float* xp = xsb + icl * 102 + px0;
            ull P[3][6];
            #pragma unroll
            for (int rr = 0; rr < 3; rr++) {
                float2 p0 = *(const float2*)(xp + rr * 34);
                float2 p1 = *(const float2*)(xp + rr * 34 + 2);
                float2 p2 = *(const float2*)(xp + rr * 34 + 4);
                P[rr][0] = pk2(p0.x); P[rr][1] = pk2(p0.y);
                P[rr][2] = pk2(p1.x); P[rr][3] = pk2(p1.y);
                P[rr][4] = pk2(p2.x); P[rr][5] = pk2(p2.y);
            }
            #pragma unroll
            for (int dy = 0; dy < 3; dy++) {
                #pragma unroll
                for (int dx = 0; dx < 3; dx++) {
                    const float* row = wsb + (icl * 9 + dy * 3 + dx) * 98 + oc0;
                    ull w01 = *(const ull*)(row);
                    ull w23 = *(const ull*)(row + 2);
                    ull w45 = *(const ull*)(row + 4);
                    ull pa = P[dy][dx];
                    ull pb = P[dy][dx + 1];
                    ull pc = P[dy][dx + 2];
                    ull pd = P[dy][dx + 3];
                    fma2(acc[0][0], w01, pa); fma2(acc[0][1], w01, pb);
                    fma2(acc[0][2], w01, pc); fma2(acc[0][3], w01, pd);
                    fma2(acc[1][0], w23, pa); fma2(acc[1][1], w23, pb);
                    fma2(acc[1][2], w23, pc); fma2(acc[1][3], w23, pd);
                    fma2(acc[2][0], w45, pa); fma2(acc[2][1], w45, pb);
                    fma2(acc[2][2], w45, pc); fma2(acc[2][3], w45, pd);
                }
            }
        }

        if (c < 15) {
            float* xdst = xs2[(c + 1) & 1];
            #pragma unroll
            for (int s = 0; s < 4; s++)
                if (s_ok[s]) xdst[s_row[s] * 34 + s_j[s]] = xstage[s];
            asm volatile("cp.async.wait_group 0;");
        }
        __syncthreads();
    }

    float dtv = __ldg(dtp);
    int pbase = y * 64 + x0 + px0;

    #pragma unroll
    for (int p = 0; p < 3; p++) {
        #pragma unroll
        for (int half = 0; half < 2; half++) {
            int oc = oc0 + 2 * p + half;
            float av[4];
            #pragma unroll
            for (int q = 0; q < 4; q++) {
                float2 v = up2(acc[p][q]);
                av[q] = half ? v.y : v.x;
            }
            if (oc < 64) {
                float bias = bd[oc] + dtv;
                float4 o4;
                float* pv = &o4.x;
                #pragma unroll
                for (int q = 0; q < 4; q++) {
                    float v = av[q] + bias;
                    float sp = (v > 0.f) ? (v + log1pf(expf(-v))) : log1pf(expf(v));
                    pv[q] = fminf(fmaxf(sp, 1e-4f), 5.0f);
                }
                *(float4*)(g_delta + (b * 64 + oc) * HW + pbase) = o4;
            } else if (oc < 80) {
                *(float4*)(g_Bval + (b * 16 + (oc - 64)) * HW + pbase) =
                    make_float4(av[0], av[1], av[2], av[3]);
            } else {
                *(float4*)(g_Cval + (b * 16 + (oc - 80)) * HW + pbase) =
                    make_float4(av[0], av[1], av[2], av[3]);
            }
        }
    }
}

// ---------------------------------------------------------------------------
// K3: circulant matmuls with cp.async-pipelined state reads.
// mx plane streams into Ms during phase-1 compute; my streams during phase 2.
// ---------------------------------------------------------------------------
__global__ void __launch_bounds__(128, 5) k_update(
        const float* __restrict__ u, const float* __restrict__ sprev,
        const float* __restrict__ logA, float* __restrict__ out) {
    __shared__ float Xs[64 * 68];    // X[r][c] at r*68 + c + 2*(c>>5)  17.4KB
    __shared__ float Ms[4096];       // staging: mx then my             16KB
    __shared__ float hb[144];        // h[i mod 64]

    int tid = threadIdx.x;
    int bp  = blockIdx.x;            // b*1024 + d*16 + n
    int b = bp >> 10, d = (bp >> 4) & 63, n = bp & 15;

    int p0 = (((b * 3 + 0) * 64 + d) * 16 + n) * HW;
    int p1 = p0 + 64 * 16 * HW;
    int p2 = p1 + 64 * 16 * HW;
    const float4* m0p4 = (const float4*)(sprev + p0);

    unsigned ms_sm = (unsigned)__cvta_generic_to_shared(Ms);

    // stream mx plane into Ms (overlaps with m0 load + phase-1 compute)
    {
        const float4* mxp = (const float4*)(sprev + p1);
        #pragma unroll
        for (int s = 0; s < 8; s++) {
            int i = tid + 128 * s;
            asm volatile("cp.async.cg.shared.global [%0], [%1], 16;"
                         :: "r"(ms_sm + i * 16), "l"(mxp + i));
        }
        asm volatile("cp.async.commit_group;");
    }

    #pragma unroll
    for (int s = 0; s < 8; s++) {
        int l4 = tid + 128 * s;              // < 1024
        float4 v = m0p4[l4];
        int idx = l4 * 4;
        int r = idx >> 6, cc = idx & 63;
        float* xsp = &Xs[r * 68 + cc + 2 * (cc >> 5)];
        *(float2*)xsp       = make_float2(v.x, v.y);
        *(float2*)(xsp + 2) = make_float2(v.z, v.w);
    }
    for (int i = tid; i < 144; i += 128) hb[i] = g_h[i & 63];
    __syncthreads();

    float Ad = -expf(__ldg(&logA[d * 16 + n]));
    int off_bd = (b * 64 + d) * HW;
    int off_bn = (b * 16 + n) * HW;
    const int so = NB * DM * HW;

    // ===== Phase 1: Gx[r][c] = sum_k X[r][k] h[c-k], 4 rows x 8 cols =====
    {
        int rg = tid >> 3, cg = tid & 7;    // rg 0..15, cg 0..7
        int r0 = rg * 4, c0 = cg * 8;
        int gap2 = 2 * (c0 >> 5);

        ull a[2][8];
        #pragma unroll
        for (int p = 0; p < 2; p++)
            #pragma unroll
            for (int j = 0; j < 8; j++) a[p][j] = 0ull;

        #pragma unroll 1
        for (int k8 = 0; k8 < 64; k8 += 8) {
            ull hl[15];
            int hbase = c0 - k8 + 57;       // in [1,113]
            #pragma unroll
            for (int m = 0; m < 15; m++) hl[m] = pk2(hb[hbase + m]);
            int gk = 2 * (k8 >> 5);
            #pragma unroll
            for (int kk2 = 0; kk2 < 4; kk2++) {
                int xo = k8 + kk2 * 2 + gk;     // even, no gap crossing
                float2 xr0 = *(const float2*)&Xs[(r0 + 0) * 68 + xo];
                float2 xr1 = *(const float2*)&Xs[(r0 + 1) * 68 + xo];
                float2 xr2 = *(const float2*)&Xs[(r0 + 2) * 68 + xo];
                float2 xr3 = *(const float2*)&Xs[(r0 + 3) * 68 + xo];
                {   // kk = 2*kk2
                    int kk = kk2 * 2;
                    ull x01 = pk(xr0.x, xr1.x), x23 = pk(xr2.x, xr3.x);
                    #pragma unroll
                    for (int j = 0; j < 8; j++) {
                        fma2(a[0][j], x01, hl[j - kk + 7]);
                        fma2(a[1][j], x23, hl[j - kk + 7]);
                    }
                }
                {   // kk = 2*kk2+1
                    int kk = kk2 * 2 + 1;
                    ull x01 = pk(xr0.y, xr1.y), x23 = pk(xr2.y, xr3.y);
                    #pragma unroll
                    for (int j = 0; j < 8; j++) {
                        fma2(a[0][j], x01, hl[j - kk + 7]);
                        fma2(a[1][j], x23, hl[j - kk + 7]);
                    }
                }
            }
        }

        // mx is now resident in Ms
        asm volatile("cp.async.wait_group 0;");
        __syncthreads();

        // epilogue: m0_new, mx_new
        #pragma unroll
        for (int i = 0; i < 4; i++) {
            int row = r0 + i;
            int off = row * 64 + c0;
            float4 dv0 = *(const float4*)(g_delta + off_bd + off);
            float4 dv1 = *(const float4*)(g_delta + off_bd + off + 4);
            float4 uv0 = *(const float4*)(u + off_bd + off);
            float4 uv1 = *(const float4*)(u + off_bd + off + 4);
            float4 bv0 = *(const float4*)(g_Bval + off_bn + off);
            float4 bv1 = *(const float4*)(g_Bval + off_bn + off + 4);
            float4 mx0 = *(const float4*)&Ms[off];
            float4 mx1 = *(const float4*)&Ms[off + 4];
            float dd[8] = { dv0.x, dv0.y, dv0.z, dv0.w, dv1.x, dv1.y, dv1.z, dv1.w };
            float uu[8] = { uv0.x, uv0.y, uv0.z, uv0.w, uv1.x, uv1.y, uv1.z, uv1.w };
            float bb[8] = { bv0.x, bv0.y, bv0.z, bv0.w, bv1.x, bv1.y, bv1.z, bv1.w };
            float mx[8] = { mx0.x, mx0.y, mx0.z, mx0.w, mx1.x, mx1.y, mx1.z, mx1.w };
            float m0n[8], mxn[8];
            #pragma unroll
            for (int j = 0; j < 8; j++) {
                float2 tt = up2(a[i >> 1][j]);
                float gx = (i & 1) ? tt.y : tt.x;
                float m0v = Xs[row * 68 + c0 + j + gap2];
                float Ab = __expf(dd[j] * Ad);
                m0n[j] = fmaf(Ab, m0v, dd[j] * bb[j] * uu[j]);
                mxn[j] = Ab * (mx[j] - gx);
            }
            *(float4*)(out + so + p0 + off)     = make_float4(m0n[0], m0n[1], m0n[2], m0n[3]);
            *(float4*)(out + so + p0 + off + 4) = make_float4(m0n[4], m0n[5], m0n[6], m0n[7]);
            *(float4*)(out + so + p1 + off)     = make_float4(mxn[0], mxn[1], mxn[2], mxn[3]);
            *(float4*)(out + so + p1 + off + 4) = make_float4(mxn[4], mxn[5], mxn[6], mxn[7]);
        }
    }

    // all threads done reading Ms (mx); refill with my during phase 2
    __syncthreads();
    {
        const float4* myp = (const float4*)(sprev + p2);
        #pragma unroll
        for (int s = 0; s < 8; s++) {
            int i = tid + 128 * s;
            asm volatile("cp.async.cg.shared.global [%0], [%1], 16;"
                         :: "r"(ms_sm + i * 16), "l"(myp + i));
        }
        asm volatile("cp.async.commit_group;");
    }

    // ===== Phase 2: Gy[r][c] = sum_k h[r-k] X[k][c], 8 rows x 4 cols =====
    {
        int rg2 = tid >> 4, cg2 = tid & 15;   // rg2 0..7, cg2 0..15
        int r0 = rg2 * 8, c0 = cg2 * 4;
        int gapc = 2 * (c0 >> 5);

        ull g2[8][2];
        #pragma unroll
        for (int i = 0; i < 8; i++) { g2[i][0] = 0ull; g2[i][1] = 0ull; }

        #pragma unroll 1
        for (int k8 = 0; k8 < 64; k8 += 8) {
            ull gl[15];
            int gb = r0 - k8 + 57;            // in [1,120]
            #pragma unroll
            for (int m = 0; m < 15; m++) gl[m] = pk2(hb[gb + m]);
            #pragma unroll
            for (int kk = 0; kk < 8; kk++) {
                int ro = (k8 + kk) * 68 + c0 + gapc;   // even -> 8B aligned
                ull xq0 = *(const ull*)&Xs[ro];
                ull xq1 = *(const ull*)&Xs[ro + 2];
                #pragma unroll
                for (int i = 0; i < 8; i++) {
                    fma2(g2[i][0], gl[i - kk + 7], xq0);
                    fma2(g2[i][1], gl[i - kk + 7], xq1);
                }
            }
        }

        // my is now resident in Ms
        asm volatile("cp.async.wait_group 0;");
        __syncthreads();

        // epilogue: my_new (A_bar recomputed; delta tile is L2-resident)
        #pragma unroll
        for (int i = 0; i < 8; i++) {
            int row = r0 + i;
            int off = row * 64 + c0;
            float4 dv = *(const float4*)(g_delta + off_bd + off);
            float4 my = *(const float4*)&Ms[off];
            float2 t0 = up2(g2[i][0]);
            float2 t1 = up2(g2[i][1]);
            float4 myn;
            myn.x = __expf(dv.x * Ad) * (my.x - t0.x);
            myn.y = __expf(dv.y * Ad) * (my.y - t0.y);
            myn.z = __expf(dv.z * Ad) * (my.z - t1.x);
            myn.w = __expf(dv.w * Ad) * (my.w - t1.y);
            *(float4*)(out + so + p2 + off) = myn;
        }
    }
}

// ---------------------------------------------------------------------------
// K4: y[b,d,p] = sum_n m0_new[b,d,n,p] * C_val[b,n,p] + u*D[d]  (float4)
// ---------------------------------------------------------------------------
__global__ void k_y(const float* __restrict__ u, const float* __restrict__ Dp,
                    float* __restrict__ out) {
    int idx4 = blockIdx.x * 256 + threadIdx.x;   // < 262144
    int b = idx4 >> 16;
    int d = (idx4 >> 10) & 63;
    int p4 = idx4 & 1023;
    const int so = NB * DM * HW;
    const float4* m0n = (const float4*)(out + so + ((b * 3 * 64 + d) * 16) * HW) + p4;
    const float4* Cv  = (const float4*)(g_Cval + (b * 16) * HW) + p4;
    float4 a = make_float4(0.f, 0.f, 0.f, 0.f);
    #pragma unroll
    for (int nn = 0; nn < 16; nn++) {
        float4 m = m0n[nn * 1024];
        float4 c = Cv[nn * 1024];
        a.x = fmaf(m.x, c.x, a.x); a.y = fmaf(m.y, c.y, a.y);
        a.z = fmaf(m.z, c.z, a.z); a.w = fmaf(m.w, c.w, a.w);
    }
    float Dd = Dp[d];
    float4 uv = ((const float4*)u)[idx4];
    a.x = fmaf(uv.x, Dd, a.x); a.y = fmaf(uv.y, Dd, a.y);
    a.z = fmaf(uv.z, Dd, a.z); a.w = fmaf(uv.w, Dd, a.w);
    ((float4*)out)[idx4] = a;
}

// ---------------------------------------------------------------------------
extern "C" void kernel_launch(void* const* d_in, const int* in_sizes, int n_in,
                              void* d_out, int out_size) {
    const float* u     = (const float*)d_in[0];
    const float* sprev = (const float*)d_in[1];
    const float* gamma = (const float*)d_in[2];
    const float* beta  = (const float*)d_in[3];
    const float* wd    = (const float*)d_in[4];
    const float* bd    = (const float*)d_in[5];
    const float* wB    = (const float*)d_in[6];
    const float* wC    = (const float*)d_in[7];
    const float* logA  = (const float*)d_in[8];
    const float* Dp    = (const float*)d_in[9];
    const float* dt    = (const float*)d_in[10];
    float* out = (float*)d_out;

    k_wprep<<<221, 256>>>(wd, wB, wC);
    k_stats<<<256, 256>>>(u);
    k_conv<<<512, 128>>>(u, gamma, beta, bd, dt);
    k_update<<<4096, 128>>>(u, sprev, logA, out);
    k_y<<<1024, 256>>>(u, Dp, out);
}